// round 2
// baseline (speedup 1.0000x reference)
#include <cuda_runtime.h>
#include <cuda_bf16.h>
#include <math_constants.h>

// Problem constants
#define BB 2
#define TT 2048
#define CC 2048
#define NH 16
#define DH 128
#define BT (BB * TT)        // 4096
#define NQKV (3 * CC)       // 6144

// Scratch (device globals; allocation is forbidden)
__device__ float g_Q[BB * NH * TT * DH];   // [B,H,T,D]
__device__ float g_K[BB * NH * TT * DH];
__device__ float g_V[BB * NH * TT * DH];
__device__ float g_AO[BB * TT * CC];       // [B,T,C] attention output

// ---------------------------------------------------------------------------
// SGEMM 128x128x16, 256 threads, 8x8 per thread.
// MODE 0: C = x @ Wqkv, scatter into g_Q/g_K/g_V ([B,H,T,D])
// MODE 1: C = g_AO @ Wout, plain row-major write to C
// ---------------------------------------------------------------------------
template <int MODE>
__global__ __launch_bounds__(256) void sgemm_kernel(
    const float* __restrict__ A, const float* __restrict__ Bm,
    float* __restrict__ C, int M, int N, int K)
{
    __shared__ float As[16 * 132];   // transposed A tile [k][m], padded
    __shared__ float Bs[16 * 128];   // B tile [k][n]

    const int tid = threadIdx.x;
    const int tx = tid & 15;
    const int ty = tid >> 4;
    const int rowBase = blockIdx.y * 128;
    const int colBase = blockIdx.x * 128;

    if (MODE == 1) A = g_AO;

    float acc[8][8];
#pragma unroll
    for (int i = 0; i < 8; i++)
#pragma unroll
        for (int j = 0; j < 8; j++) acc[i][j] = 0.f;

    for (int k0 = 0; k0 < K; k0 += 16) {
        // load A tile (128x16) -> transposed smem. 512 float4s over 2 iters.
#pragma unroll
        for (int l = 0; l < 2; l++) {
            int idx = tid + l * 256;
            int ar = idx >> 2, ac4 = idx & 3;
            float4 v = *(const float4*)&A[(size_t)(rowBase + ar) * K + k0 + ac4 * 4];
            As[(ac4 * 4 + 0) * 132 + ar] = v.x;
            As[(ac4 * 4 + 1) * 132 + ar] = v.y;
            As[(ac4 * 4 + 2) * 132 + ar] = v.z;
            As[(ac4 * 4 + 3) * 132 + ar] = v.w;
        }
        // load B tile (16x128). 512 float4s: row = idx>>5 (0..15), col4 = idx&31.
#pragma unroll
        for (int l = 0; l < 2; l++) {
            int idx = tid + l * 256;
            int br = idx >> 5, bc4 = idx & 31;
            *(float4*)&Bs[br * 128 + bc4 * 4] =
                *(const float4*)&Bm[(size_t)(k0 + br) * N + colBase + bc4 * 4];
        }
        __syncthreads();

#pragma unroll
        for (int k = 0; k < 16; k++) {
            float af[8], bf[8];
            *(float4*)&af[0] = *(float4*)&As[k * 132 + ty * 8];
            *(float4*)&af[4] = *(float4*)&As[k * 132 + ty * 8 + 4];
            *(float4*)&bf[0] = *(float4*)&Bs[k * 128 + tx * 8];
            *(float4*)&bf[4] = *(float4*)&Bs[k * 128 + tx * 8 + 4];
#pragma unroll
            for (int i = 0; i < 8; i++)
#pragma unroll
                for (int j = 0; j < 8; j++)
                    acc[i][j] = fmaf(af[i], bf[j], acc[i][j]);
        }
        __syncthreads();
    }

    if (MODE == 0) {
        // scatter into Q/K/V [B,H,T,D]
#pragma unroll
        for (int i = 0; i < 8; i++) {
            int m = rowBase + ty * 8 + i;
            int b = m >> 11;           // /2048
            int t = m & 2047;
            int ncol = colBase + tx * 8;   // 8 contiguous cols, head-aligned
            int which = ncol >> 11;        // 0=q,1=k,2=v
            int c = ncol & 2047;
            int h = c >> 7;
            int d = c & 127;
            float* dst = (which == 0) ? g_Q : (which == 1) ? g_K : g_V;
            size_t base = ((size_t)((b * NH + h) * TT + t)) * DH + d;
            *(float4*)&dst[base]     = make_float4(acc[i][0], acc[i][1], acc[i][2], acc[i][3]);
            *(float4*)&dst[base + 4] = make_float4(acc[i][4], acc[i][5], acc[i][6], acc[i][7]);
        }
    } else {
#pragma unroll
        for (int i = 0; i < 8; i++) {
            int m = rowBase + ty * 8 + i;
            size_t base = (size_t)m * N + colBase + tx * 8;
            *(float4*)&C[base]     = make_float4(acc[i][0], acc[i][1], acc[i][2], acc[i][3]);
            *(float4*)&C[base + 4] = make_float4(acc[i][4], acc[i][5], acc[i][6], acc[i][7]);
        }
    }
}

// ---------------------------------------------------------------------------
// Flash attention (causal), fp32. BM=BN=64, D=128, 256 threads.
// grid: (T/64, B*H). Online softmax; output into g_AO [B,T,C].
// ---------------------------------------------------------------------------
#define FLASH_SMEM_FLOATS (64*132 + 128*68 + 64*132 + 64*68 + 3*64)
#define FLASH_SMEM_BYTES  (FLASH_SMEM_FLOATS * 4)

__global__ __launch_bounds__(256) void flash_kernel()
{
    extern __shared__ float sm[];
    float* Qs  = sm;                 // [64][132]
    float* Kts = Qs  + 64 * 132;     // [128][68]  K transposed
    float* Vs  = Kts + 128 * 68;     // [64][132]
    float* Ss  = Vs  + 64 * 132;     // [64][68]
    float* mrow = Ss + 64 * 68;      // [64]
    float* lrow = mrow + 64;         // [64]
    float* arow = lrow + 64;         // [64]

    const int bh = blockIdx.y;                        // b*16+h
    const int qt = (int)gridDim.x - 1 - (int)blockIdx.x;  // long blocks first
    const int tid = threadIdx.x;
    const int tx = tid & 15;
    const int ty = tid >> 4;

    const float* Qb = g_Q + (size_t)bh * TT * DH;
    const float* Kb = g_K + (size_t)bh * TT * DH;
    const float* Vb = g_V + (size_t)bh * TT * DH;

    const float scale = 0.08838834764831845f;  // 1/sqrt(128)
    const float NEG_INF = __int_as_float(0xff800000);

    // load Q tile (64x128 = 2048 float4s)
#pragma unroll
    for (int l = 0; l < 8; l++) {
        int idx = tid + l * 256;
        int r = idx >> 5, c4 = idx & 31;
        float4 v = *(const float4*)&Qb[(size_t)(qt * 64 + r) * DH + c4 * 4];
        *(float4*)&Qs[r * 132 + c4 * 4] = v;
    }
    if (tid < 64) { mrow[tid] = NEG_INF; lrow[tid] = 0.f; }

    float oacc[4][8];
#pragma unroll
    for (int i = 0; i < 4; i++)
#pragma unroll
        for (int j = 0; j < 8; j++) oacc[i][j] = 0.f;

    for (int j = 0; j <= qt; j++) {
        // load K (transposed) and V tiles
#pragma unroll
        for (int l = 0; l < 8; l++) {
            int idx = tid + l * 256;
            int r = idx >> 5, c4 = idx & 31;
            float4 kv = *(const float4*)&Kb[(size_t)(j * 64 + r) * DH + c4 * 4];
            Kts[(c4 * 4 + 0) * 68 + r] = kv.x;
            Kts[(c4 * 4 + 1) * 68 + r] = kv.y;
            Kts[(c4 * 4 + 2) * 68 + r] = kv.z;
            Kts[(c4 * 4 + 3) * 68 + r] = kv.w;
            float4 vv = *(const float4*)&Vb[(size_t)(j * 64 + r) * DH + c4 * 4];
            *(float4*)&Vs[r * 132 + c4 * 4] = vv;
        }
        __syncthreads();

        // S = Q @ K^T  (thread: 4x4 micro-tile)
        float sacc[4][4];
#pragma unroll
        for (int i = 0; i < 4; i++)
#pragma unroll
            for (int jj = 0; jj < 4; jj++) sacc[i][jj] = 0.f;

#pragma unroll 4
        for (int d = 0; d < 128; d++) {
            float qf[4], kf[4];
#pragma unroll
            for (int i = 0; i < 4; i++) qf[i] = Qs[(ty * 4 + i) * 132 + d];
            *(float4*)kf = *(float4*)&Kts[d * 68 + tx * 4];
#pragma unroll
            for (int i = 0; i < 4; i++)
#pragma unroll
                for (int jj = 0; jj < 4; jj++)
                    sacc[i][jj] = fmaf(qf[i], kf[jj], sacc[i][jj]);
        }

        const bool diag = (j == qt);
#pragma unroll
        for (int i = 0; i < 4; i++) {
            int lr = ty * 4 + i;
            int qrow = qt * 64 + lr;
            float4 sv;
            float* s4 = (float*)&sv;
#pragma unroll
            for (int jj = 0; jj < 4; jj++) {
                int kcol = j * 64 + tx * 4 + jj;
                float s = sacc[i][jj] * scale;
                if (diag && kcol > qrow) s = NEG_INF;
                s4[jj] = s;
            }
            *(float4*)&Ss[lr * 68 + tx * 4] = sv;
        }
        __syncthreads();

        // online softmax update (4 threads per row, 16 cols each)
        {
            int row = tid >> 2, part = tid & 3;
            float* sp = &Ss[row * 68 + part * 16];
            float lm = NEG_INF;
#pragma unroll
            for (int c = 0; c < 16; c++) lm = fmaxf(lm, sp[c]);
            lm = fmaxf(lm, __shfl_xor_sync(0xffffffffu, lm, 1));
            lm = fmaxf(lm, __shfl_xor_sync(0xffffffffu, lm, 2));
            float mo = mrow[row];
            float mn = fmaxf(mo, lm);
            float ls = 0.f;
#pragma unroll
            for (int c = 0; c < 16; c++) {
                float p = __expf(sp[c] - mn);
                sp[c] = p;
                ls += p;
            }
            ls += __shfl_xor_sync(0xffffffffu, ls, 1);
            ls += __shfl_xor_sync(0xffffffffu, ls, 2);
            if (part == 0) {
                float al = __expf(mo - mn);
                arow[row] = al;
                mrow[row] = mn;
                lrow[row] = lrow[row] * al + ls;
            }
        }
        __syncthreads();

        // O = O*alpha + P @ V
        float al[4];
#pragma unroll
        for (int i = 0; i < 4; i++) al[i] = arow[ty * 4 + i];
#pragma unroll
        for (int i = 0; i < 4; i++)
#pragma unroll
            for (int jj = 0; jj < 8; jj++) oacc[i][jj] *= al[i];

#pragma unroll 4
        for (int kk = 0; kk < 64; kk++) {
            float pf[4], vf[8];
#pragma unroll
            for (int i = 0; i < 4; i++) pf[i] = Ss[(ty * 4 + i) * 68 + kk];
            *(float4*)&vf[0] = *(float4*)&Vs[kk * 132 + tx * 8];
            *(float4*)&vf[4] = *(float4*)&Vs[kk * 132 + tx * 8 + 4];
#pragma unroll
            for (int i = 0; i < 4; i++)
#pragma unroll
                for (int jj = 0; jj < 8; jj++)
                    oacc[i][jj] = fmaf(pf[i], vf[jj], oacc[i][jj]);
        }
        __syncthreads();
    }

    // epilogue: normalize, write to g_AO [B,T,C]
    const int b = bh >> 4;
    const int h = bh & 15;
#pragma unroll
    for (int i = 0; i < 4; i++) {
        int lr = ty * 4 + i;
        float inv = 1.0f / lrow[lr];
        int qrow = qt * 64 + lr;
        size_t base = ((size_t)(b * TT + qrow)) * CC + h * DH + tx * 8;
        *(float4*)&g_AO[base] = make_float4(oacc[i][0] * inv, oacc[i][1] * inv,
                                            oacc[i][2] * inv, oacc[i][3] * inv);
        *(float4*)&g_AO[base + 4] = make_float4(oacc[i][4] * inv, oacc[i][5] * inv,
                                                oacc[i][6] * inv, oacc[i][7] * inv);
    }
}

// ---------------------------------------------------------------------------
extern "C" void kernel_launch(void* const* d_in, const int* in_sizes, int n_in,
                              void* d_out, int out_size)
{
    const float* x    = (const float*)d_in[0];
    // d_in[1] is the boolean causal mask -> implemented analytically, unused
    const float* Wqkv = (const float*)d_in[2];
    const float* Wout = (const float*)d_in[3];
    float* out = (float*)d_out;

    // 1) QKV projection with scatter into [B,H,T,D]
    sgemm_kernel<0><<<dim3(NQKV / 128, BT / 128), 256>>>(x, Wqkv, nullptr, BT, NQKV, CC);

    // 2) causal flash attention
    cudaFuncSetAttribute(flash_kernel, cudaFuncAttributeMaxDynamicSharedMemorySize,
                         FLASH_SMEM_BYTES);
    flash_kernel<<<dim3(TT / 64, BB * NH), 256, FLASH_SMEM_BYTES>>>();

    // 3) output projection
    sgemm_kernel<1><<<dim3(CC / 128, BT / 128), 256>>>(nullptr, Wout, out, BT, CC, CC);
}

// round 4
// speedup vs baseline: 1.3996x; 1.3996x over previous
#include <cuda_runtime.h>
#include <cuda_bf16.h>
#include <cstdint>

// Problem constants
#define BB 2
#define TT 2048
#define CC 2048
#define NH 16
#define DH 128
#define BT (BB * TT)        // 4096
#define NQKV (3 * CC)       // 6144
#define KDIM 2048
#define KC 64
#define NKC (KDIM / KC)     // 32
#define TM 128
#define TN 256

// tcgen05 only exists in the arch-specific (sm_103a/sm_100a) compilation pass.
#if defined(__CUDA_ARCH_FEAT_SM103_ALL) || defined(__CUDA_ARCH_FEAT_SM100_ALL) || defined(__CUDA_ARCH_FEAT_SM101_ALL)
#define USE_TCGEN05 1
#else
#define USE_TCGEN05 0
#endif

// ---------------------------------------------------------------------------
// Scratch (device globals; allocation is forbidden)
// ---------------------------------------------------------------------------
__device__ float g_Q[BB * NH * TT * DH];   // [B,H,T,D]
__device__ float g_K[BB * NH * TT * DH];
__device__ float g_V[BB * NH * TT * DH];
__device__ float g_AO[BB * TT * CC];       // [B,T,C]

// blocked, pre-swizzled bf16 operands (hi/lo split)
__device__ __align__(128) __nv_bfloat16 gA_hi[BT * KDIM];
__device__ __align__(128) __nv_bfloat16 gA_lo[BT * KDIM];
__device__ __align__(128) __nv_bfloat16 gAO_hi[BT * KDIM];
__device__ __align__(128) __nv_bfloat16 gAO_lo[BT * KDIM];
__device__ __align__(128) __nv_bfloat16 gBq_hi[KDIM * NQKV];
__device__ __align__(128) __nv_bfloat16 gBq_lo[KDIM * NQKV];
__device__ __align__(128) __nv_bfloat16 gBo_hi[KDIM * CC];
__device__ __align__(128) __nv_bfloat16 gBo_lo[KDIM * CC];

// ---------------------------------------------------------------------------
// Helpers
// ---------------------------------------------------------------------------
#define SWZ128(o) ((o) ^ (((o) >> 3) & 0x70))

__device__ __forceinline__ uint32_t smem_u32(const void* p) {
    uint32_t a;
    asm("{ .reg .u64 t; cvta.to.shared.u64 t, %1; cvt.u32.u64 %0, t; }" : "=r"(a) : "l"(p));
    return a;
}

#if USE_TCGEN05
static constexpr uint64_t SMEM_DESC_BASE_SW128 =
    (uint64_t(2) << 61) | (uint64_t(1) << 46) | (uint64_t(64) << 32) | (uint64_t(1) << 16);
#define MAKE_SMEM_DESC(base_addr) \
    (SMEM_DESC_BASE_SW128 | ((uint64_t)((base_addr) >> 4) & 0x3FFF))

__device__ __forceinline__ uint32_t elect1() {
    uint32_t p;
    asm volatile("{\n\t.reg .pred p;\n\telect.sync _|p, 0xFFFFFFFF;\n\tselp.b32 %0, 1, 0, p;\n\t}" : "=r"(p));
    return p;
}
__device__ __forceinline__ void mbar_init(uint32_t a, uint32_t c) {
    asm volatile("mbarrier.init.shared.b64 [%0], %1;" :: "r"(a), "r"(c) : "memory");
}
__device__ __forceinline__ void mbar_expect(uint32_t a, uint32_t tx) {
    asm volatile("mbarrier.arrive.expect_tx.shared.b64 _, [%0], %1;" :: "r"(a), "r"(tx) : "memory");
}
__device__ __forceinline__ void mbar_arrive(uint32_t a) {
    asm volatile("mbarrier.arrive.release.cta.shared.b64 _, [%0];" :: "r"(a) : "memory");
}
__device__ __forceinline__ void mbar_wait_acq(uint32_t a, uint32_t ph) {
    asm volatile(
        "{\n\t.reg .pred P;\n"
        "WL_%=:\n\t"
        "mbarrier.try_wait.parity.acquire.cta.shared::cta.b64 P, [%0], %1, 0x989680;\n\t"
        "@P bra WD_%=;\n\t"
        "bra WL_%=;\n"
        "WD_%=:\n\t}"
        :: "r"(a), "r"(ph) : "memory");
}
__device__ __forceinline__ void mbar_wait_rlx(uint32_t a, uint32_t ph) {
    asm volatile(
        "{\n\t.reg .pred P;\n"
        "WL_%=:\n\t"
        "mbarrier.try_wait.parity.relaxed.cta.shared::cta.b64 P, [%0], %1, 0x989680;\n\t"
        "@P bra WD_%=;\n\t"
        "bra WL_%=;\n"
        "WD_%=:\n\t}"
        :: "r"(a), "r"(ph) : "memory");
}
__device__ __forceinline__ void bulk_g2s(uint32_t dst, const void* src, uint32_t n, uint32_t mbar) {
    asm volatile(
        "cp.async.bulk.shared::cta.global.mbarrier::complete_tx::bytes [%0], [%1], %2, [%3];"
        :: "r"(dst), "l"(src), "r"(n), "r"(mbar) : "memory");
}
__device__ __forceinline__ void tc_alloc(uint32_t smem_res, uint32_t ncols) {
    asm volatile("tcgen05.alloc.cta_group::1.sync.aligned.shared::cta.b32 [%0], %1;"
                 :: "r"(smem_res), "r"(ncols) : "memory");
}
__device__ __forceinline__ void tc_dealloc(uint32_t tmem, uint32_t ncols) {
    asm volatile("tcgen05.dealloc.cta_group::1.sync.aligned.b32 %0, %1;" :: "r"(tmem), "r"(ncols));
}
__device__ __forceinline__ void tc_commit(uint32_t mbar) {
    asm volatile("tcgen05.commit.cta_group::1.mbarrier::arrive::one.shared::cluster.b64 [%0];"
                 :: "r"(mbar) : "memory");
}
__device__ __forceinline__ void tc_fence_after() {
    asm volatile("tcgen05.fence::after_thread_sync;" ::: "memory");
}
__device__ __forceinline__ void tc_wait_ld() {
    asm volatile("tcgen05.wait::ld.sync.aligned;" ::: "memory");
}
__device__ __forceinline__ void mma_f16_ss(uint32_t d, uint64_t a, uint64_t b, uint32_t idesc, uint32_t en) {
    asm volatile(
        "{\n\t.reg .pred p;\n\t"
        "setp.ne.u32 p, %5, 0;\n\t"
        "tcgen05.mma.cta_group::1.kind::f16 [%0], %1, %2, %3, {%4, %4, %4, %4}, p;\n\t}"
        :: "r"(d), "l"(a), "l"(b), "r"(idesc), "r"(0u), "r"(en) : "memory");
}
#define TC_LD_32X32B_X32(r, tmem_addr) \
    asm volatile( \
        "tcgen05.ld.sync.aligned.32x32b.x32.b32 " \
        "{%0, %1, %2, %3, %4, %5, %6, %7, " \
        " %8, %9, %10, %11, %12, %13, %14, %15, " \
        " %16, %17, %18, %19, %20, %21, %22, %23, " \
        " %24, %25, %26, %27, %28, %29, %30, %31}, [%32];" \
        : "=r"((r)[0]),  "=r"((r)[1]),  "=r"((r)[2]),  "=r"((r)[3]), \
          "=r"((r)[4]),  "=r"((r)[5]),  "=r"((r)[6]),  "=r"((r)[7]), \
          "=r"((r)[8]),  "=r"((r)[9]),  "=r"((r)[10]), "=r"((r)[11]), \
          "=r"((r)[12]), "=r"((r)[13]), "=r"((r)[14]), "=r"((r)[15]), \
          "=r"((r)[16]), "=r"((r)[17]), "=r"((r)[18]), "=r"((r)[19]), \
          "=r"((r)[20]), "=r"((r)[21]), "=r"((r)[22]), "=r"((r)[23]), \
          "=r"((r)[24]), "=r"((r)[25]), "=r"((r)[26]), "=r"((r)[27]), \
          "=r"((r)[28]), "=r"((r)[29]), "=r"((r)[30]), "=r"((r)[31]) \
        : "r"(tmem_addr))

// idesc kind::f16: dtype F32 (bit4), atype BF16 (bit7), btype BF16 (bit10),
// N/8 at bit17 (256/8=32), M/16 at bit24 (128/16=8)
#define MM_IDESC ((1u<<4) | (1u<<7) | (1u<<10) | (32u<<17) | (8u<<24))
#endif // USE_TCGEN05

// ---------------------------------------------------------------------------
// Conversion kernels: fp32 -> blocked, SW128-swizzled bf16 hi/lo tiles.
// A-style: src [M rows][2048 k] -> [mtile][kc][128 x 64] 16KB blocks
// ---------------------------------------------------------------------------
__global__ __launch_bounds__(256) void convA_kernel(
    const float* __restrict__ src, __nv_bfloat16* __restrict__ hi, __nv_bfloat16* __restrict__ lo)
{
    int e = blockIdx.x * 256 + threadIdx.x;
    int m = e >> 8;
    int k = (e & 255) << 3;
    float v[8];
    *(float4*)&v[0] = *(const float4*)&src[(size_t)m * KDIM + k];
    *(float4*)&v[4] = *(const float4*)&src[(size_t)m * KDIM + k + 4];
    __nv_bfloat16 hb[8], lb[8];
#pragma unroll
    for (int i = 0; i < 8; i++) {
        hb[i] = __float2bfloat16(v[i]);
        lb[i] = __float2bfloat16(v[i] - __bfloat162float(hb[i]));
    }
    int mt = m >> 7, r = m & 127, kc = k >> 6, kcol = k & 63;
    size_t blk = ((size_t)(mt * NKC + kc)) * 8192;      // elements
    uint32_t off = SWZ128((uint32_t)(r * 128 + kcol * 2));
    *(uint4*)((char*)hi + blk * 2 + off) = *(uint4*)hb;
    *(uint4*)((char*)lo + blk * 2 + off) = *(uint4*)lb;
}

// B-style: W [2048 k][N n] -> transposed blocked [ntile][kc][256 x 64] 32KB blocks
__global__ __launch_bounds__(256) void convB_kernel(
    const float* __restrict__ W, int N,
    __nv_bfloat16* __restrict__ hi, __nv_bfloat16* __restrict__ lo)
{
    int n = blockIdx.x * 256 + threadIdx.x;
    int k = blockIdx.y * 8;
    float v[8];
#pragma unroll
    for (int i = 0; i < 8; i++) v[i] = W[(size_t)(k + i) * N + n];
    __nv_bfloat16 hb[8], lb[8];
#pragma unroll
    for (int i = 0; i < 8; i++) {
        hb[i] = __float2bfloat16(v[i]);
        lb[i] = __float2bfloat16(v[i] - __bfloat162float(hb[i]));
    }
    int nt = n >> 8, nr = n & 255, kc = k >> 6, kcol = k & 63;
    size_t blk = ((size_t)(nt * NKC + kc)) * 16384;
    uint32_t off = SWZ128((uint32_t)(nr * 128 + kcol * 2));
    *(uint4*)((char*)hi + blk * 2 + off) = *(uint4*)hb;
    *(uint4*)((char*)lo + blk * 2 + off) = *(uint4*)lb;
}

// ---------------------------------------------------------------------------
// GEMM: 128x256 tile/CTA.
//  - sm_103a pass: tcgen05 bf16x3, 2-stage cp.async.bulk pipeline.
//  - generic pass: SIMT fp32 fallback (hi+lo reconstruct), same inputs/outputs.
// MODE 0: scatter into g_Q/g_K/g_V.  MODE 1: row-major fp32 out.
// ---------------------------------------------------------------------------
#define STAGE_BYTES 98304               // Ahi16K + Alo16K + Bhi32K + Blo32K
#define MM_SMEM (1024 + 2 * STAGE_BYTES)

template <int MODE>
__global__ __launch_bounds__(128) void mm_kernel(
    const __nv_bfloat16* __restrict__ Ahi, const __nv_bfloat16* __restrict__ Alo,
    const __nv_bfloat16* __restrict__ Bhi, const __nv_bfloat16* __restrict__ Blo,
    float* __restrict__ Cout)
{
    extern __shared__ char smem[];
    const int tid = threadIdx.x;
    const int nt = blockIdx.x, mt = blockIdx.y;

#if USE_TCGEN05
    __shared__ __align__(8) uint64_t s_ctrl[8];   // [0]=tmem ptr, [1..5]=mbarriers
    const uint32_t TMP  = smem_u32(&s_ctrl[0]);
    const uint32_t FUL0 = smem_u32(&s_ctrl[1]);
    const uint32_t FUL1 = smem_u32(&s_ctrl[2]);
    const uint32_t DON0 = smem_u32(&s_ctrl[3]);
    const uint32_t DON1 = smem_u32(&s_ctrl[4]);
    const uint32_t FIN  = smem_u32(&s_ctrl[5]);

    const uint32_t sb = smem_u32(smem);
    const uint32_t ab = (sb + 1023u) & ~1023u;          // 1024-aligned stages
    char* smA = smem + (ab - sb);
    const int wid = tid >> 5, lane = tid & 31;

    if (wid == 0) tc_alloc(TMP, 256);
    if (tid == 0) {
        mbar_init(FUL0, 1); mbar_init(FUL1, 1);
        mbar_init(DON0, 1); mbar_init(DON1, 1);
        mbar_init(FIN, 1);
    }
    __syncthreads();
    uint32_t tmem;
    asm volatile("ld.shared.b32 %0, [%1];" : "=r"(tmem) : "r"(TMP));

    const size_t aBase = (size_t)mt * NKC * 8192;    // elements
    const size_t bBase = (size_t)nt * NKC * 16384;

    if (wid == 0) {
        const uint32_t ep = elect1();
        uint32_t st_base[2] = { ab, ab + STAGE_BYTES };
        uint32_t ful[2] = { FUL0, FUL1 };
        uint32_t don[2] = { DON0, DON1 };
        int fph[2] = {0, 0}, dph[2] = {0, 0};

        if (ep) {
#pragma unroll
            for (int s = 0; s < 2; s++) {
                mbar_expect(ful[s], STAGE_BYTES);
                bulk_g2s(st_base[s],         Ahi + aBase + (size_t)s * 8192, 16384, ful[s]);
                bulk_g2s(st_base[s] + 16384, Alo + aBase + (size_t)s * 8192, 16384, ful[s]);
                bulk_g2s(st_base[s] + 32768, Bhi + bBase + (size_t)s * 16384, 32768, ful[s]);
                bulk_g2s(st_base[s] + 65536, Blo + bBase + (size_t)s * 16384, 32768, ful[s]);
            }
        }
        for (int kc = 0; kc < NKC; kc++) {
            int st = kc & 1;
            mbar_wait_rlx(ful[st], fph[st]); fph[st] ^= 1;
            if (ep) {
                uint64_t ah = MAKE_SMEM_DESC(st_base[st]);
                uint64_t al = MAKE_SMEM_DESC(st_base[st] + 16384);
                uint64_t bh = MAKE_SMEM_DESC(st_base[st] + 32768);
                uint64_t bl = MAKE_SMEM_DESC(st_base[st] + 65536);
#pragma unroll
                for (int ks = 0; ks < 4; ks++) {
                    uint32_t first = (kc == 0 && ks == 0) ? 0u : 1u;
                    mma_f16_ss(tmem, ah + ks * 2, bh + ks * 2, MM_IDESC, first);
                    mma_f16_ss(tmem, ah + ks * 2, bl + ks * 2, MM_IDESC, 1u);
                    mma_f16_ss(tmem, al + ks * 2, bh + ks * 2, MM_IDESC, 1u);
                }
                tc_commit(don[st]);
            }
            int pv = kc - 1;
            if (pv >= 0 && pv + 2 < NKC) {
                int ps = pv & 1;
                mbar_wait_rlx(don[ps], dph[ps]); dph[ps] ^= 1;
                if (ep) {
                    size_t nk = (size_t)(pv + 2);
                    mbar_expect(ful[ps], STAGE_BYTES);
                    bulk_g2s(st_base[ps],         Ahi + aBase + nk * 8192, 16384, ful[ps]);
                    bulk_g2s(st_base[ps] + 16384, Alo + aBase + nk * 8192, 16384, ful[ps]);
                    bulk_g2s(st_base[ps] + 32768, Bhi + bBase + nk * 16384, 32768, ful[ps]);
                    bulk_g2s(st_base[ps] + 65536, Blo + bBase + nk * 16384, 32768, ful[ps]);
                }
            }
        }
        // drain both done barriers (one outstanding commit each), then signal epilogue
        mbar_wait_rlx(don[0], dph[0]);
        mbar_wait_rlx(don[1], dph[1]);
        if (ep) mbar_arrive(FIN);
    }

    mbar_wait_acq(FIN, 0);
    tc_fence_after();

    // epilogue: LDTM -> smem transpose -> coalesced fp32 stores
    float* sbuf = (float*)smA + wid * (32 * 33);
    const int mBase = mt * TM + wid * 32;
    const int nBase = nt * TN;
#pragma unroll 1
    for (int ch = 0; ch < 8; ch++) {
        uint32_t r[32];
        TC_LD_32X32B_X32(r, tmem + ch * 32);
        tc_wait_ld();
#pragma unroll
        for (int c = 0; c < 32; c++) sbuf[lane * 33 + c] = __uint_as_float(r[c]);
        __syncwarp();
        int ncol0 = nBase + ch * 32;
        if (MODE == 0) {
            int which = ncol0 >> 11;
            int cc = ncol0 & 2047;
            int h = cc >> 7, d0 = cc & 127;
            float* dst = (which == 0) ? g_Q : (which == 1) ? g_K : g_V;
#pragma unroll 4
            for (int rr = 0; rr < 32; rr++) {
                int m = mBase + rr;
                int b = m >> 11, t = m & 2047;
                dst[((size_t)(b * NH + h) * TT + t) * DH + d0 + lane] = sbuf[rr * 33 + lane];
            }
        } else {
#pragma unroll 4
            for (int rr = 0; rr < 32; rr++) {
                int m = mBase + rr;
                Cout[(size_t)m * CC + ncol0 + lane] = sbuf[rr * 33 + lane];
            }
        }
        __syncwarp();
    }
    __syncthreads();
    if (wid == 0) tc_dealloc(tmem, 256);

#else  // ------------- generic SIMT fallback (correct, slower) -------------
    float* As = (float*)smem;                  // [128][65]
    float* Bs = As + 128 * 65;                 // [64][65]
    const int tx = tid & 7;                    // 8 n-octets
    const int ty = tid >> 3;                   // 16 m-groups of 8 rows

    for (int nch = 0; nch < 4; nch++) {        // 64-col chunks of 256
        float acc[8][8];
#pragma unroll
        for (int i = 0; i < 8; i++)
#pragma unroll
            for (int j = 0; j < 8; j++) acc[i][j] = 0.f;

        for (int kc = 0; kc < NKC; kc++) {
            const char* abh = (const char*)Ahi + ((size_t)(mt * NKC + kc)) * 16384;
            const char* abl = (const char*)Alo + ((size_t)(mt * NKC + kc)) * 16384;
            for (int i = tid; i < 8192; i += 128) {
                int r = i >> 6, c = i & 63;
                uint32_t off = SWZ128((uint32_t)(r * 128 + c * 2));
                As[r * 65 + c] = __bfloat162float(*(const __nv_bfloat16*)(abh + off))
                               + __bfloat162float(*(const __nv_bfloat16*)(abl + off));
            }
            const char* bbh = (const char*)Bhi + ((size_t)(nt * NKC + kc)) * 32768;
            const char* bbl = (const char*)Blo + ((size_t)(nt * NKC + kc)) * 32768;
            for (int i = tid; i < 4096; i += 128) {
                int r = i >> 6, c = i & 63;
                int gr = nch * 64 + r;
                uint32_t off = SWZ128((uint32_t)(gr * 128 + c * 2));
                Bs[r * 65 + c] = __bfloat162float(*(const __nv_bfloat16*)(bbh + off))
                               + __bfloat162float(*(const __nv_bfloat16*)(bbl + off));
            }
            __syncthreads();
#pragma unroll 4
            for (int k = 0; k < KC; k++) {
                float af[8], bf[8];
#pragma unroll
                for (int i = 0; i < 8; i++) af[i] = As[(ty * 8 + i) * 65 + k];
#pragma unroll
                for (int j = 0; j < 8; j++) bf[j] = Bs[(tx * 8 + j) * 65 + k];
#pragma unroll
                for (int i = 0; i < 8; i++)
#pragma unroll
                    for (int j = 0; j < 8; j++)
                        acc[i][j] = fmaf(af[i], bf[j], acc[i][j]);
            }
            __syncthreads();
        }
#pragma unroll
        for (int i = 0; i < 8; i++) {
            int m = mt * TM + ty * 8 + i;
#pragma unroll
            for (int j = 0; j < 8; j++) {
                int n = nt * TN + nch * 64 + tx * 8 + j;
                if (MODE == 0) {
                    int which = n >> 11, c = n & 2047;
                    int h = c >> 7, d = c & 127;
                    int b = m >> 11, t = m & 2047;
                    float* dst = (which == 0) ? g_Q : (which == 1) ? g_K : g_V;
                    dst[((size_t)(b * NH + h) * TT + t) * DH + d] = acc[i][j];
                } else {
                    Cout[(size_t)m * CC + n] = acc[i][j];
                }
            }
        }
        __syncthreads();
    }
#endif
}

// ---------------------------------------------------------------------------
// Flash attention (causal), fp32 — unchanged from passing round-2 kernel.
// ---------------------------------------------------------------------------
#define FLASH_SMEM_FLOATS (64*132 + 128*68 + 64*132 + 64*68 + 3*64)
#define FLASH_SMEM_BYTES  (FLASH_SMEM_FLOATS * 4)

__global__ __launch_bounds__(256) void flash_kernel()
{
    extern __shared__ float sm[];
    float* Qs  = sm;
    float* Kts = Qs  + 64 * 132;
    float* Vs  = Kts + 128 * 68;
    float* Ss  = Vs  + 64 * 132;
    float* mrow = Ss + 64 * 68;
    float* lrow = mrow + 64;
    float* arow = lrow + 64;

    const int bh = blockIdx.y;
    const int qt = (int)gridDim.x - 1 - (int)blockIdx.x;
    const int tid = threadIdx.x;
    const int tx = tid & 15;
    const int ty = tid >> 4;

    const float* Qb = g_Q + (size_t)bh * TT * DH;
    const float* Kb = g_K + (size_t)bh * TT * DH;
    const float* Vb = g_V + (size_t)bh * TT * DH;

    const float scale = 0.08838834764831845f;
    const float NEG_INF = __int_as_float(0xff800000);

#pragma unroll
    for (int l = 0; l < 8; l++) {
        int idx = tid + l * 256;
        int r = idx >> 5, c4 = idx & 31;
        float4 v = *(const float4*)&Qb[(size_t)(qt * 64 + r) * DH + c4 * 4];
        *(float4*)&Qs[r * 132 + c4 * 4] = v;
    }
    if (tid < 64) { mrow[tid] = NEG_INF; lrow[tid] = 0.f; }

    float oacc[4][8];
#pragma unroll
    for (int i = 0; i < 4; i++)
#pragma unroll
        for (int j = 0; j < 8; j++) oacc[i][j] = 0.f;

    for (int j = 0; j <= qt; j++) {
#pragma unroll
        for (int l = 0; l < 8; l++) {
            int idx = tid + l * 256;
            int r = idx >> 5, c4 = idx & 31;
            float4 kv = *(const float4*)&Kb[(size_t)(j * 64 + r) * DH + c4 * 4];
            Kts[(c4 * 4 + 0) * 68 + r] = kv.x;
            Kts[(c4 * 4 + 1) * 68 + r] = kv.y;
            Kts[(c4 * 4 + 2) * 68 + r] = kv.z;
            Kts[(c4 * 4 + 3) * 68 + r] = kv.w;
            float4 vv = *(const float4*)&Vb[(size_t)(j * 64 + r) * DH + c4 * 4];
            *(float4*)&Vs[r * 132 + c4 * 4] = vv;
        }
        __syncthreads();

        float sacc[4][4];
#pragma unroll
        for (int i = 0; i < 4; i++)
#pragma unroll
            for (int jj = 0; jj < 4; jj++) sacc[i][jj] = 0.f;

#pragma unroll 4
        for (int d = 0; d < 128; d++) {
            float qf[4], kf[4];
#pragma unroll
            for (int i = 0; i < 4; i++) qf[i] = Qs[(ty * 4 + i) * 132 + d];
            *(float4*)kf = *(float4*)&Kts[d * 68 + tx * 4];
#pragma unroll
            for (int i = 0; i < 4; i++)
#pragma unroll
                for (int jj = 0; jj < 4; jj++)
                    sacc[i][jj] = fmaf(qf[i], kf[jj], sacc[i][jj]);
        }

        const bool diag = (j == qt);
#pragma unroll
        for (int i = 0; i < 4; i++) {
            int lr = ty * 4 + i;
            int qrow = qt * 64 + lr;
            float4 sv;
            float* s4 = (float*)&sv;
#pragma unroll
            for (int jj = 0; jj < 4; jj++) {
                int kcol = j * 64 + tx * 4 + jj;
                float s = sacc[i][jj] * scale;
                if (diag && kcol > qrow) s = NEG_INF;
                s4[jj] = s;
            }
            *(float4*)&Ss[lr * 68 + tx * 4] = sv;
        }
        __syncthreads();

        {
            int row = tid >> 2, part = tid & 3;
            float* sp = &Ss[row * 68 + part * 16];
            float lm = NEG_INF;
#pragma unroll
            for (int c = 0; c < 16; c++) lm = fmaxf(lm, sp[c]);
            lm = fmaxf(lm, __shfl_xor_sync(0xffffffffu, lm, 1));
            lm = fmaxf(lm, __shfl_xor_sync(0xffffffffu, lm, 2));
            float mo = mrow[row];
            float mn = fmaxf(mo, lm);
            float ls = 0.f;
#pragma unroll
            for (int c = 0; c < 16; c++) {
                float p = __expf(sp[c] - mn);
                sp[c] = p;
                ls += p;
            }
            ls += __shfl_xor_sync(0xffffffffu, ls, 1);
            ls += __shfl_xor_sync(0xffffffffu, ls, 2);
            if (part == 0) {
                float al = __expf(mo - mn);
                arow[row] = al;
                mrow[row] = mn;
                lrow[row] = lrow[row] * al + ls;
            }
        }
        __syncthreads();

        float al[4];
#pragma unroll
        for (int i = 0; i < 4; i++) al[i] = arow[ty * 4 + i];
#pragma unroll
        for (int i = 0; i < 4; i++)
#pragma unroll
            for (int jj = 0; jj < 8; jj++) oacc[i][jj] *= al[i];

#pragma unroll 4
        for (int kk = 0; kk < 64; kk++) {
            float pf[4], vf[8];
#pragma unroll
            for (int i = 0; i < 4; i++) pf[i] = Ss[(ty * 4 + i) * 68 + kk];
            *(float4*)&vf[0] = *(float4*)&Vs[kk * 132 + tx * 8];
            *(float4*)&vf[4] = *(float4*)&Vs[kk * 132 + tx * 8 + 4];
#pragma unroll
            for (int i = 0; i < 4; i++)
#pragma unroll
                for (int jj = 0; jj < 8; jj++)
                    oacc[i][jj] = fmaf(pf[i], vf[jj], oacc[i][jj]);
        }
        __syncthreads();
    }

    const int b = bh >> 4;
    const int h = bh & 15;
#pragma unroll
    for (int i = 0; i < 4; i++) {
        int lr = ty * 4 + i;
        float inv = 1.0f / lrow[lr];
        int qrow = qt * 64 + lr;
        size_t base = ((size_t)(b * TT + qrow)) * CC + h * DH + tx * 8;
        *(float4*)&g_AO[base] = make_float4(oacc[i][0] * inv, oacc[i][1] * inv,
                                            oacc[i][2] * inv, oacc[i][3] * inv);
        *(float4*)&g_AO[base + 4] = make_float4(oacc[i][4] * inv, oacc[i][5] * inv,
                                                oacc[i][6] * inv, oacc[i][7] * inv);
    }
}

// ---------------------------------------------------------------------------
extern "C" void kernel_launch(void* const* d_in, const int* in_sizes, int n_in,
                              void* d_out, int out_size)
{
    const float* x    = (const float*)d_in[0];
    const float* Wqkv = (const float*)d_in[2];
    const float* Wout = (const float*)d_in[3];
    float* out = (float*)d_out;

    cudaFuncSetAttribute(mm_kernel<0>, cudaFuncAttributeMaxDynamicSharedMemorySize, MM_SMEM);
    cudaFuncSetAttribute(mm_kernel<1>, cudaFuncAttributeMaxDynamicSharedMemorySize, MM_SMEM);
    cudaFuncSetAttribute(flash_kernel, cudaFuncAttributeMaxDynamicSharedMemorySize,
                         FLASH_SMEM_BYTES);

    __nv_bfloat16 *pAhi, *pAlo, *pAOhi, *pAOlo, *pBqhi, *pBqlo, *pBohi, *pBolo;
    cudaGetSymbolAddress((void**)&pAhi,  gA_hi);
    cudaGetSymbolAddress((void**)&pAlo,  gA_lo);
    cudaGetSymbolAddress((void**)&pAOhi, gAO_hi);
    cudaGetSymbolAddress((void**)&pAOlo, gAO_lo);
    cudaGetSymbolAddress((void**)&pBqhi, gBq_hi);
    cudaGetSymbolAddress((void**)&pBqlo, gBq_lo);
    cudaGetSymbolAddress((void**)&pBohi, gBo_hi);
    cudaGetSymbolAddress((void**)&pBolo, gBo_lo);
    float* pAO;
    cudaGetSymbolAddress((void**)&pAO, g_AO);

    // 1) convert operands
    convA_kernel<<<4096, 256>>>(x, pAhi, pAlo);
    convB_kernel<<<dim3(NQKV / 256, KDIM / 8), 256>>>(Wqkv, NQKV, pBqhi, pBqlo);
    convB_kernel<<<dim3(CC / 256, KDIM / 8), 256>>>(Wout, CC, pBohi, pBolo);

    // 2) QKV projection (bf16x3), scatter to [B,H,T,D]
    mm_kernel<0><<<dim3(NQKV / TN, BT / TM), 128, MM_SMEM>>>(pAhi, pAlo, pBqhi, pBqlo, nullptr);

    // 3) causal flash attention (fp32)
    flash_kernel<<<dim3(TT / 64, BB * NH), 256, FLASH_SMEM_BYTES>>>();

    // 4) convert AO, output projection
    convA_kernel<<<4096, 256>>>(pAO, pAOhi, pAOlo);
    mm_kernel<1><<<dim3(CC / TN, BT / TM), 128, MM_SMEM>>>(pAOhi, pAOlo, pBohi, pBolo, out);
}

// round 5
// speedup vs baseline: 6.8510x; 4.8949x over previous
#include <cuda_runtime.h>
#include <cuda_bf16.h>
#include <cuda_fp16.h>
#include <cstdint>

// Problem constants
#define BB 2
#define TT 2048
#define CC 2048
#define NH 16
#define DH 128
#define BT (BB * TT)        // 4096
#define NQKV (3 * CC)       // 6144
#define KDIM 2048
#define KC 64
#define NKC (KDIM / KC)     // 32
#define TM 128
#define TN 256

#if defined(__CUDA_ARCH_FEAT_SM103_ALL) || defined(__CUDA_ARCH_FEAT_SM100_ALL) || defined(__CUDA_ARCH_FEAT_SM101_ALL)
#define USE_TCGEN05 1
#else
#define USE_TCGEN05 0
#endif

// ---------------------------------------------------------------------------
// Scratch (device globals; allocation is forbidden)
// ---------------------------------------------------------------------------
__device__ float g_Q[BB * NH * TT * DH];   // [B,H,T,D]
__device__ float g_K[BB * NH * TT * DH];
__device__ float g_V[BB * NH * TT * DH];
__device__ float g_AO[BB * TT * CC];       // [B,T,C]

// blocked, pre-swizzled bf16 operands (hi/lo split) for the projections
__device__ __align__(128) __nv_bfloat16 gA_hi[BT * KDIM];
__device__ __align__(128) __nv_bfloat16 gA_lo[BT * KDIM];
__device__ __align__(128) __nv_bfloat16 gAO_hi[BT * KDIM];
__device__ __align__(128) __nv_bfloat16 gAO_lo[BT * KDIM];
__device__ __align__(128) __nv_bfloat16 gBq_hi[KDIM * NQKV];
__device__ __align__(128) __nv_bfloat16 gBq_lo[KDIM * NQKV];
__device__ __align__(128) __nv_bfloat16 gBo_hi[KDIM * CC];
__device__ __align__(128) __nv_bfloat16 gBo_lo[KDIM * CC];

// blocked, pre-swizzled fp16 hi/lo attention tiles (32KB per 128x128 tile)
__device__ __align__(128) __half gQh[BB * NH * TT * DH];
__device__ __align__(128) __half gQl[BB * NH * TT * DH];
__device__ __align__(128) __half gKh[BB * NH * TT * DH];
__device__ __align__(128) __half gKl[BB * NH * TT * DH];
__device__ __align__(128) __half gVh[BB * NH * TT * DH];   // V^T tiles
__device__ __align__(128) __half gVl[BB * NH * TT * DH];

// ---------------------------------------------------------------------------
// Helpers
// ---------------------------------------------------------------------------
#define SWZ128(o) ((o) ^ (((o) >> 3) & 0x70))

__device__ __forceinline__ uint32_t smem_u32(const void* p) {
    uint32_t a;
    asm("{ .reg .u64 t; cvta.to.shared.u64 t, %1; cvt.u32.u64 %0, t; }" : "=r"(a) : "l"(p));
    return a;
}

#if USE_TCGEN05
static constexpr uint64_t SMEM_DESC_BASE_SW128 =
    (uint64_t(2) << 61) | (uint64_t(1) << 46) | (uint64_t(64) << 32) | (uint64_t(1) << 16);
#define MAKE_SMEM_DESC(base_addr) \
    (SMEM_DESC_BASE_SW128 | ((uint64_t)((base_addr) >> 4) & 0x3FFF))

__device__ __forceinline__ uint32_t elect1() {
    uint32_t p;
    asm volatile("{\n\t.reg .pred p;\n\telect.sync _|p, 0xFFFFFFFF;\n\tselp.b32 %0, 1, 0, p;\n\t}" : "=r"(p));
    return p;
}
__device__ __forceinline__ void mbar_init(uint32_t a, uint32_t c) {
    asm volatile("mbarrier.init.shared.b64 [%0], %1;" :: "r"(a), "r"(c) : "memory");
}
__device__ __forceinline__ void mbar_expect(uint32_t a, uint32_t tx) {
    asm volatile("mbarrier.arrive.expect_tx.shared.b64 _, [%0], %1;" :: "r"(a), "r"(tx) : "memory");
}
__device__ __forceinline__ void mbar_arrive(uint32_t a) {
    asm volatile("mbarrier.arrive.release.cta.shared.b64 _, [%0];" :: "r"(a) : "memory");
}
__device__ __forceinline__ void mbar_wait_acq(uint32_t a, uint32_t ph) {
    asm volatile(
        "{\n\t.reg .pred P;\n"
        "WL_%=:\n\t"
        "mbarrier.try_wait.parity.acquire.cta.shared::cta.b64 P, [%0], %1, 0x989680;\n\t"
        "@P bra WD_%=;\n\t"
        "bra WL_%=;\n"
        "WD_%=:\n\t}"
        :: "r"(a), "r"(ph) : "memory");
}
__device__ __forceinline__ void mbar_wait_rlx(uint32_t a, uint32_t ph) {
    asm volatile(
        "{\n\t.reg .pred P;\n"
        "WL_%=:\n\t"
        "mbarrier.try_wait.parity.relaxed.cta.shared::cta.b64 P, [%0], %1, 0x989680;\n\t"
        "@P bra WD_%=;\n\t"
        "bra WL_%=;\n"
        "WD_%=:\n\t}"
        :: "r"(a), "r"(ph) : "memory");
}
__device__ __forceinline__ void bulk_g2s(uint32_t dst, const void* src, uint32_t n, uint32_t mbar) {
    asm volatile(
        "cp.async.bulk.shared::cta.global.mbarrier::complete_tx::bytes [%0], [%1], %2, [%3];"
        :: "r"(dst), "l"(src), "r"(n), "r"(mbar) : "memory");
}
__device__ __forceinline__ void tc_alloc(uint32_t smem_res, uint32_t ncols) {
    asm volatile("tcgen05.alloc.cta_group::1.sync.aligned.shared::cta.b32 [%0], %1;"
                 :: "r"(smem_res), "r"(ncols) : "memory");
}
__device__ __forceinline__ void tc_dealloc(uint32_t tmem, uint32_t ncols) {
    asm volatile("tcgen05.dealloc.cta_group::1.sync.aligned.b32 %0, %1;" :: "r"(tmem), "r"(ncols));
}
__device__ __forceinline__ void tc_commit(uint32_t mbar) {
    asm volatile("tcgen05.commit.cta_group::1.mbarrier::arrive::one.shared::cluster.b64 [%0];"
                 :: "r"(mbar) : "memory");
}
__device__ __forceinline__ void tc_fence_before() {
    asm volatile("tcgen05.fence::before_thread_sync;" ::: "memory");
}
__device__ __forceinline__ void tc_fence_after() {
    asm volatile("tcgen05.fence::after_thread_sync;" ::: "memory");
}
__device__ __forceinline__ void tc_wait_ld() {
    asm volatile("tcgen05.wait::ld.sync.aligned;" ::: "memory");
}
__device__ __forceinline__ void tc_wait_st() {
    asm volatile("tcgen05.wait::st.sync.aligned;" ::: "memory");
}
__device__ __forceinline__ void mma_f16_ss(uint32_t d, uint64_t a, uint64_t b, uint32_t idesc, uint32_t en) {
    asm volatile(
        "{\n\t.reg .pred p;\n\t"
        "setp.ne.u32 p, %5, 0;\n\t"
        "tcgen05.mma.cta_group::1.kind::f16 [%0], %1, %2, %3, {%4, %4, %4, %4}, p;\n\t}"
        :: "r"(d), "l"(a), "l"(b), "r"(idesc), "r"(0u), "r"(en) : "memory");
}
__device__ __forceinline__ void mma_f16_ts(uint32_t d, uint32_t a, uint64_t b, uint32_t idesc, uint32_t en) {
    asm volatile(
        "{\n\t.reg .pred p;\n\t"
        "setp.ne.u32 p, %5, 0;\n\t"
        "tcgen05.mma.cta_group::1.kind::f16 [%0], [%1], %2, %3, {%4, %4, %4, %4}, p;\n\t}"
        :: "r"(d), "r"(a), "l"(b), "r"(idesc), "r"(0u), "r"(en) : "memory");
}
#define TC_LD_32X32B_X32(r, tmem_addr) \
    asm volatile( \
        "tcgen05.ld.sync.aligned.32x32b.x32.b32 " \
        "{%0, %1, %2, %3, %4, %5, %6, %7, " \
        " %8, %9, %10, %11, %12, %13, %14, %15, " \
        " %16, %17, %18, %19, %20, %21, %22, %23, " \
        " %24, %25, %26, %27, %28, %29, %30, %31}, [%32];" \
        : "=r"((r)[0]),  "=r"((r)[1]),  "=r"((r)[2]),  "=r"((r)[3]), \
          "=r"((r)[4]),  "=r"((r)[5]),  "=r"((r)[6]),  "=r"((r)[7]), \
          "=r"((r)[8]),  "=r"((r)[9]),  "=r"((r)[10]), "=r"((r)[11]), \
          "=r"((r)[12]), "=r"((r)[13]), "=r"((r)[14]), "=r"((r)[15]), \
          "=r"((r)[16]), "=r"((r)[17]), "=r"((r)[18]), "=r"((r)[19]), \
          "=r"((r)[20]), "=r"((r)[21]), "=r"((r)[22]), "=r"((r)[23]), \
          "=r"((r)[24]), "=r"((r)[25]), "=r"((r)[26]), "=r"((r)[27]), \
          "=r"((r)[28]), "=r"((r)[29]), "=r"((r)[30]), "=r"((r)[31]) \
        : "r"(tmem_addr))
#define TC_ST_32X32B_X32(tmem_addr, r) \
    asm volatile( \
        "tcgen05.st.sync.aligned.32x32b.x32.b32 [%0], " \
        "{%1, %2, %3, %4, %5, %6, %7, %8, " \
        " %9, %10, %11, %12, %13, %14, %15, %16, " \
        " %17, %18, %19, %20, %21, %22, %23, %24, " \
        " %25, %26, %27, %28, %29, %30, %31, %32};" \
        :: "r"(tmem_addr), \
           "r"((r)[0]),  "r"((r)[1]),  "r"((r)[2]),  "r"((r)[3]), \
           "r"((r)[4]),  "r"((r)[5]),  "r"((r)[6]),  "r"((r)[7]), \
           "r"((r)[8]),  "r"((r)[9]),  "r"((r)[10]), "r"((r)[11]), \
           "r"((r)[12]), "r"((r)[13]), "r"((r)[14]), "r"((r)[15]), \
           "r"((r)[16]), "r"((r)[17]), "r"((r)[18]), "r"((r)[19]), \
           "r"((r)[20]), "r"((r)[21]), "r"((r)[22]), "r"((r)[23]), \
           "r"((r)[24]), "r"((r)[25]), "r"((r)[26]), "r"((r)[27]), \
           "r"((r)[28]), "r"((r)[29]), "r"((r)[30]), "r"((r)[31]) \
        : "memory")

// bf16 GEMM idesc: dtype F32, atype/btype BF16, N=256, M=128
#define MM_IDESC ((1u<<4) | (1u<<7) | (1u<<10) | (32u<<17) | (8u<<24))
// fp16 attention idesc: dtype F32, atype/btype F16(0), N=128, M=128
#define FA_IDESC ((1u<<4) | (16u<<17) | (8u<<24))
#endif // USE_TCGEN05

// ---------------------------------------------------------------------------
// Conversion kernels for the projections (bf16 hi/lo, unchanged)
// ---------------------------------------------------------------------------
__global__ __launch_bounds__(256) void convA_kernel(
    const float* __restrict__ src, __nv_bfloat16* __restrict__ hi, __nv_bfloat16* __restrict__ lo)
{
    int e = blockIdx.x * 256 + threadIdx.x;
    int m = e >> 8;
    int k = (e & 255) << 3;
    float v[8];
    *(float4*)&v[0] = *(const float4*)&src[(size_t)m * KDIM + k];
    *(float4*)&v[4] = *(const float4*)&src[(size_t)m * KDIM + k + 4];
    __nv_bfloat16 hb[8], lb[8];
#pragma unroll
    for (int i = 0; i < 8; i++) {
        hb[i] = __float2bfloat16(v[i]);
        lb[i] = __float2bfloat16(v[i] - __bfloat162float(hb[i]));
    }
    int mt = m >> 7, r = m & 127, kc = k >> 6, kcol = k & 63;
    size_t blk = ((size_t)(mt * NKC + kc)) * 8192;
    uint32_t off = SWZ128((uint32_t)(r * 128 + kcol * 2));
    *(uint4*)((char*)hi + blk * 2 + off) = *(uint4*)hb;
    *(uint4*)((char*)lo + blk * 2 + off) = *(uint4*)lb;
}

__global__ __launch_bounds__(256) void convB_kernel(
    const float* __restrict__ W, int N,
    __nv_bfloat16* __restrict__ hi, __nv_bfloat16* __restrict__ lo)
{
    int n = blockIdx.x * 256 + threadIdx.x;
    int k = blockIdx.y * 8;
    float v[8];
#pragma unroll
    for (int i = 0; i < 8; i++) v[i] = W[(size_t)(k + i) * N + n];
    __nv_bfloat16 hb[8], lb[8];
#pragma unroll
    for (int i = 0; i < 8; i++) {
        hb[i] = __float2bfloat16(v[i]);
        lb[i] = __float2bfloat16(v[i] - __bfloat162float(hb[i]));
    }
    int nt = n >> 8, nr = n & 255, kc = k >> 6, kcol = k & 63;
    size_t blk = ((size_t)(nt * NKC + kc)) * 16384;
    uint32_t off = SWZ128((uint32_t)(nr * 128 + kcol * 2));
    *(uint4*)((char*)hi + blk * 2 + off) = *(uint4*)hb;
    *(uint4*)((char*)lo + blk * 2 + off) = *(uint4*)lb;
}

// ---------------------------------------------------------------------------
// Conversion kernels for attention: fp32 [B,H,T,D] -> blocked SW128 fp16 hi/lo.
// Tile = 128x128 fp16 = 32KB: atom 8x64, 16 atom-rows, 2 atom-cols.
// ---------------------------------------------------------------------------
__global__ __launch_bounds__(256) void convQK_kernel(
    const float* __restrict__ src, __half* __restrict__ hi, __half* __restrict__ lo, float scale)
{
    int e = blockIdx.x * 256 + threadIdx.x;     // bh(5) | t(11) | d8(4)
    int d8 = e & 15;
    int t = (e >> 4) & 2047;
    int bh = e >> 15;
    size_t flat = ((size_t)bh * TT + t) * DH + d8 * 8;
    float v[8];
    *(float4*)&v[0] = *(const float4*)&src[flat];
    *(float4*)&v[4] = *(const float4*)&src[flat + 4];
    __half hb[8], lb[8];
#pragma unroll
    for (int i = 0; i < 8; i++) {
        float f = v[i] * scale;
        __half h = __float2half_rn(f);
        hb[i] = h;
        lb[i] = __float2half_rn(f - __half2float(h));
    }
    int tile = t >> 7, r = t & 127, d0 = d8 * 8;
    int ac = d0 >> 6, ic = d0 & 63;
    int atom = (r >> 3) + ac * 16;
    uint32_t off = SWZ128((uint32_t)(atom * 1024 + (r & 7) * 128 + ic * 2));
    size_t base = ((size_t)bh * 16 + tile) * 32768;   // bytes
    *(uint4*)((char*)hi + base + off) = *(uint4*)hb;
    *(uint4*)((char*)lo + base + off) = *(uint4*)lb;
}

// V transposed tiles: dest row = d, cols = key within tile.
__global__ __launch_bounds__(256) void convVT_kernel(
    const float* __restrict__ src, __half* __restrict__ hi, __half* __restrict__ lo)
{
    int e = blockIdx.x * 256 + threadIdx.x;     // bh(5) | t8(8) | d(7)
    int d = e & 127;
    int t0 = ((e >> 7) & 255) * 8;
    int bh = e >> 15;
    __half hb[8], lb[8];
#pragma unroll
    for (int i = 0; i < 8; i++) {
        float f = src[((size_t)bh * TT + t0 + i) * DH + d];
        __half h = __float2half_rn(f);
        hb[i] = h;
        lb[i] = __float2half_rn(f - __half2float(h));
    }
    int tile = t0 >> 7, tl = t0 & 127;
    int ac = tl >> 6, ic = tl & 63;
    int atom = (d >> 3) + ac * 16;
    uint32_t off = SWZ128((uint32_t)(atom * 1024 + (d & 7) * 128 + ic * 2));
    size_t base = ((size_t)bh * 16 + tile) * 32768;
    *(uint4*)((char*)hi + base + off) = *(uint4*)hb;
    *(uint4*)((char*)lo + base + off) = *(uint4*)lb;
}

// ---------------------------------------------------------------------------
// tcgen05 GEMM: 128x256 tile/CTA (projections) — unchanged from passing R4.
// ---------------------------------------------------------------------------
#define STAGE_BYTES 98304
#define MM_SMEM (1024 + 2 * STAGE_BYTES)

template <int MODE>
__global__ __launch_bounds__(128) void mm_kernel(
    const __nv_bfloat16* __restrict__ Ahi, const __nv_bfloat16* __restrict__ Alo,
    const __nv_bfloat16* __restrict__ Bhi, const __nv_bfloat16* __restrict__ Blo,
    float* __restrict__ Cout)
{
    extern __shared__ char smem[];
    const int tid = threadIdx.x;
    const int nt = blockIdx.x, mt = blockIdx.y;

#if USE_TCGEN05
    __shared__ __align__(8) uint64_t s_ctrl[8];
    const uint32_t TMP  = smem_u32(&s_ctrl[0]);
    const uint32_t FUL0 = smem_u32(&s_ctrl[1]);
    const uint32_t FUL1 = smem_u32(&s_ctrl[2]);
    const uint32_t DON0 = smem_u32(&s_ctrl[3]);
    const uint32_t DON1 = smem_u32(&s_ctrl[4]);
    const uint32_t FIN  = smem_u32(&s_ctrl[5]);

    const uint32_t sb = smem_u32(smem);
    const uint32_t ab = (sb + 1023u) & ~1023u;
    char* smA = smem + (ab - sb);
    const int wid = tid >> 5, lane = tid & 31;

    if (wid == 0) tc_alloc(TMP, 256);
    if (tid == 0) {
        mbar_init(FUL0, 1); mbar_init(FUL1, 1);
        mbar_init(DON0, 1); mbar_init(DON1, 1);
        mbar_init(FIN, 1);
    }
    __syncthreads();
    uint32_t tmem;
    asm volatile("ld.shared.b32 %0, [%1];" : "=r"(tmem) : "r"(TMP));

    const size_t aBase = (size_t)mt * NKC * 8192;
    const size_t bBase = (size_t)nt * NKC * 16384;

    if (wid == 0) {
        const uint32_t ep = elect1();
        uint32_t st_base[2] = { ab, ab + STAGE_BYTES };
        uint32_t ful[2] = { FUL0, FUL1 };
        uint32_t don[2] = { DON0, DON1 };
        int fph[2] = {0, 0}, dph[2] = {0, 0};

        if (ep) {
#pragma unroll
            for (int s = 0; s < 2; s++) {
                mbar_expect(ful[s], STAGE_BYTES);
                bulk_g2s(st_base[s],         Ahi + aBase + (size_t)s * 8192, 16384, ful[s]);
                bulk_g2s(st_base[s] + 16384, Alo + aBase + (size_t)s * 8192, 16384, ful[s]);
                bulk_g2s(st_base[s] + 32768, Bhi + bBase + (size_t)s * 16384, 32768, ful[s]);
                bulk_g2s(st_base[s] + 65536, Blo + bBase + (size_t)s * 16384, 32768, ful[s]);
            }
        }
        for (int kc = 0; kc < NKC; kc++) {
            int st = kc & 1;
            mbar_wait_rlx(ful[st], fph[st]); fph[st] ^= 1;
            if (ep) {
                uint64_t ah = MAKE_SMEM_DESC(st_base[st]);
                uint64_t al = MAKE_SMEM_DESC(st_base[st] + 16384);
                uint64_t bh = MAKE_SMEM_DESC(st_base[st] + 32768);
                uint64_t bl = MAKE_SMEM_DESC(st_base[st] + 65536);
#pragma unroll
                for (int ks = 0; ks < 4; ks++) {
                    uint32_t first = (kc == 0 && ks == 0) ? 0u : 1u;
                    mma_f16_ss(tmem, ah + ks * 2, bh + ks * 2, MM_IDESC, first);
                    mma_f16_ss(tmem, ah + ks * 2, bl + ks * 2, MM_IDESC, 1u);
                    mma_f16_ss(tmem, al + ks * 2, bh + ks * 2, MM_IDESC, 1u);
                }
                tc_commit(don[st]);
            }
            int pv = kc - 1;
            if (pv >= 0 && pv + 2 < NKC) {
                int ps = pv & 1;
                mbar_wait_rlx(don[ps], dph[ps]); dph[ps] ^= 1;
                if (ep) {
                    size_t nk = (size_t)(pv + 2);
                    mbar_expect(ful[ps], STAGE_BYTES);
                    bulk_g2s(st_base[ps],         Ahi + aBase + nk * 8192, 16384, ful[ps]);
                    bulk_g2s(st_base[ps] + 16384, Alo + aBase + nk * 8192, 16384, ful[ps]);
                    bulk_g2s(st_base[ps] + 32768, Bhi + bBase + nk * 16384, 32768, ful[ps]);
                    bulk_g2s(st_base[ps] + 65536, Blo + bBase + nk * 16384, 32768, ful[ps]);
                }
            }
        }
        mbar_wait_rlx(don[0], dph[0]);
        mbar_wait_rlx(don[1], dph[1]);
        if (ep) mbar_arrive(FIN);
    }

    mbar_wait_acq(FIN, 0);
    tc_fence_after();

    float* sbuf = (float*)smA + wid * (32 * 33);
    const int mBase = mt * TM + wid * 32;
    const int nBase = nt * TN;
#pragma unroll 1
    for (int ch = 0; ch < 8; ch++) {
        uint32_t r[32];
        TC_LD_32X32B_X32(r, tmem + ch * 32);
        tc_wait_ld();
#pragma unroll
        for (int c = 0; c < 32; c++) sbuf[lane * 33 + c] = __uint_as_float(r[c]);
        __syncwarp();
        int ncol0 = nBase + ch * 32;
        if (MODE == 0) {
            int which = ncol0 >> 11;
            int cc = ncol0 & 2047;
            int h = cc >> 7, d0 = cc & 127;
            float* dst = (which == 0) ? g_Q : (which == 1) ? g_K : g_V;
#pragma unroll 4
            for (int rr = 0; rr < 32; rr++) {
                int m = mBase + rr;
                int b = m >> 11, t = m & 2047;
                dst[((size_t)(b * NH + h) * TT + t) * DH + d0 + lane] = sbuf[rr * 33 + lane];
            }
        } else {
#pragma unroll 4
            for (int rr = 0; rr < 32; rr++) {
                int m = mBase + rr;
                Cout[(size_t)m * CC + ncol0 + lane] = sbuf[rr * 33 + lane];
            }
        }
        __syncwarp();
    }
    __syncthreads();
    if (wid == 0) tc_dealloc(tmem, 256);
#endif
}

// ---------------------------------------------------------------------------
// tcgen05 flash attention (causal). 128 threads; q-tile 128; key tile 128.
// TMEM: S[0..127] fp32, O[128..255] fp32, P[256..319] fp16x2.
// ---------------------------------------------------------------------------
#define FTC_SMEM (1024 + 6 * 32768)

__global__ __launch_bounds__(128, 1) void flash_tc_kernel(
    const __half* __restrict__ pQh, const __half* __restrict__ pQl,
    const __half* __restrict__ pKh, const __half* __restrict__ pKl,
    const __half* __restrict__ pVh, const __half* __restrict__ pVl)
{
#if USE_TCGEN05
    extern __shared__ char smem[];
    __shared__ __align__(8) uint64_t ctrl[8];
    const uint32_t TMP = smem_u32(&ctrl[0]);
    const uint32_t QF  = smem_u32(&ctrl[1]);
    const uint32_t KVF = smem_u32(&ctrl[2]);
    const uint32_t SD  = smem_u32(&ctrl[3]);
    const uint32_t PD  = smem_u32(&ctrl[4]);

    const int tid = threadIdx.x, wid = tid >> 5, lane = tid & 31;
    const int bh = blockIdx.y;
    const int qt = (int)gridDim.x - 1 - (int)blockIdx.x;   // long CTAs first

    const uint32_t sb = smem_u32(smem);
    const uint32_t ab = (sb + 1023u) & ~1023u;
    const uint32_t sQh = ab, sQl = ab + 32768, sKh = ab + 65536,
                   sKl = ab + 98304, sVh = ab + 131072, sVl = ab + 163840;

    if (wid == 0) tc_alloc(TMP, 512);
    if (tid == 0) { mbar_init(QF, 1); mbar_init(KVF, 1); mbar_init(SD, 1); mbar_init(PD, 1); }
    __syncthreads();
    uint32_t tmem;
    asm volatile("ld.shared.b32 %0, [%1];" : "=r"(tmem) : "r"(TMP));
    const uint32_t tS = tmem, tO = tmem + 128, tP = tmem + 256;
    const uint32_t woff = (uint32_t)wid << 21;

    const size_t headBase = (size_t)bh * 16 * 16384;       // elements; 16 tiles/head
    const size_t qOff = headBase + (size_t)qt * 16384;

    if (wid == 0 && elect1()) {
        mbar_expect(QF, 65536);
        bulk_g2s(sQh, pQh + qOff, 32768, QF);
        bulk_g2s(sQl, pQl + qOff, 32768, QF);
        mbar_expect(KVF, 131072);
        bulk_g2s(sKh, pKh + headBase, 32768, KVF);
        bulk_g2s(sKl, pKl + headBase, 32768, KVF);
        bulk_g2s(sVh, pVh + headBase, 32768, KVF);
        bulk_g2s(sVl, pVl + headBase, 32768, KVF);
    }

    const float NEG_INF = __int_as_float(0xff800000);
    float m = NEG_INF, l = 0.f;

    for (int j = 0; j <= qt; j++) {
        const int ph = j & 1;
        // ---- S = (Qh+Ql)*(Kh+Kl)^T (drop lo*lo) ----
        if (wid == 0) {
            if (j == 0) mbar_wait_rlx(QF, 0);
            mbar_wait_rlx(KVF, ph);
            if (elect1()) {
                uint64_t dQh = MAKE_SMEM_DESC(sQh), dQl = MAKE_SMEM_DESC(sQl);
                uint64_t dKh = MAKE_SMEM_DESC(sKh), dKl = MAKE_SMEM_DESC(sKl);
#pragma unroll
                for (int ks = 0; ks < 8; ks++) {
                    uint64_t o = (uint64_t)((ks & 3) * 2 + (ks >> 2) * 1024);
                    mma_f16_ss(tS, dQh + o, dKh + o, FA_IDESC, ks == 0 ? 0u : 1u);
                    mma_f16_ss(tS, dQh + o, dKl + o, FA_IDESC, 1u);
                    mma_f16_ss(tS, dQl + o, dKh + o, FA_IDESC, 1u);
                }
                tc_commit(SD);
            }
        }
        mbar_wait_acq(SD, ph);
        tc_fence_after();

        // ---- softmax: thread owns q-row (wid*32+lane) ----
        float s[128];
#pragma unroll
        for (int c4 = 0; c4 < 4; c4++)
            TC_LD_32X32B_X32(((uint32_t*)s) + c4 * 32, tS + woff + c4 * 32);
        tc_wait_ld();

        if (j == qt) {
            int qrow = wid * 32 + lane;
#pragma unroll
            for (int c = 0; c < 128; c++)
                if (c > qrow) s[c] = NEG_INF;
        }
        float mx = m;
#pragma unroll
        for (int c = 0; c < 128; c++) mx = fmaxf(mx, s[c]);
        float alpha = __expf(m - mx);
        m = mx;
        float ls = 0.f;
#pragma unroll
        for (int c = 0; c < 128; c++) {
            float p = __expf(s[c] - mx);
            s[c] = p;
            ls += p;
        }
        l = l * alpha + ls;

        // ---- P -> fp16x2 -> TMEM (A operand for PV) ----
        {
            uint32_t pk[32];
#pragma unroll
            for (int c = 0; c < 32; c++) {
                __half2 h2 = __floats2half2_rn(s[2 * c], s[2 * c + 1]);
                pk[c] = *reinterpret_cast<uint32_t*>(&h2);
            }
            TC_ST_32X32B_X32(tP + woff, pk);
#pragma unroll
            for (int c = 0; c < 32; c++) {
                __half2 h2 = __floats2half2_rn(s[64 + 2 * c], s[64 + 2 * c + 1]);
                pk[c] = *reinterpret_cast<uint32_t*>(&h2);
            }
            TC_ST_32X32B_X32(tP + woff + 32, pk);
            tc_wait_st();
        }

        // ---- O rescale (per-warp skip when all alpha==1) ----
        if (j > 0 && !__all_sync(0xffffffffu, alpha == 1.0f)) {
#pragma unroll 1
            for (int c4 = 0; c4 < 4; c4++) {
                uint32_t o[32];
                TC_LD_32X32B_X32(o, tO + woff + c4 * 32);
                tc_wait_ld();
#pragma unroll
                for (int c = 0; c < 32; c++)
                    o[c] = __float_as_uint(__uint_as_float(o[c]) * alpha);
                TC_ST_32X32B_X32(tO + woff + c4 * 32, o);
            }
            tc_wait_st();
        }
        tc_fence_before();
        __syncthreads();

        // ---- O += P * V^T (TS mode: A=P in TMEM, B=V^T hi/lo in smem) ----
        if (wid == 0 && elect1()) {
            tc_fence_after();
            uint64_t dVh = MAKE_SMEM_DESC(sVh), dVl = MAKE_SMEM_DESC(sVl);
#pragma unroll
            for (int ks = 0; ks < 8; ks++) {
                uint64_t o = (uint64_t)((ks & 3) * 2 + (ks >> 2) * 1024);
                mma_f16_ts(tO, tP + ks * 8, dVh + o, FA_IDESC, (j == 0 && ks == 0) ? 0u : 1u);
            }
#pragma unroll
            for (int ks = 0; ks < 8; ks++) {
                uint64_t o = (uint64_t)((ks & 3) * 2 + (ks >> 2) * 1024);
                mma_f16_ts(tO, tP + ks * 8, dVl + o, FA_IDESC, 1u);
            }
            tc_commit(PD);
        }
        mbar_wait_acq(PD, ph);
        tc_fence_after();

        // ---- prefetch next K/V (buffers now free) ----
        if (j < qt && wid == 0 && elect1()) {
            size_t kOff = headBase + (size_t)(j + 1) * 16384;
            mbar_expect(KVF, 131072);
            bulk_g2s(sKh, pKh + kOff, 32768, KVF);
            bulk_g2s(sKl, pKl + kOff, 32768, KVF);
            bulk_g2s(sVh, pVh + kOff, 32768, KVF);
            bulk_g2s(sVl, pVl + kOff, 32768, KVF);
        }
    }

    // ---- epilogue: O/l -> g_AO [B,T,C] via smem transpose ----
    const float invl = 1.0f / l;
    float* sbuf = (float*)(smem + (ab - sb)) + wid * (32 * 33);   // reuse Q area
    const int b = bh >> 4, h = bh & 15;
#pragma unroll 1
    for (int ch = 0; ch < 4; ch++) {
        uint32_t o[32];
        TC_LD_32X32B_X32(o, tO + woff + ch * 32);
        tc_wait_ld();
#pragma unroll
        for (int c = 0; c < 32; c++) sbuf[lane * 33 + c] = __uint_as_float(o[c]) * invl;
        __syncwarp();
#pragma unroll 4
        for (int rr = 0; rr < 32; rr++) {
            int qrow = qt * 128 + wid * 32 + rr;
            g_AO[((size_t)(b * TT + qrow)) * CC + h * DH + ch * 32 + lane] = sbuf[rr * 33 + lane];
        }
        __syncwarp();
    }
    __syncthreads();
    if (wid == 0) tc_dealloc(tmem, 512);
#endif
}

// ---------------------------------------------------------------------------
extern "C" void kernel_launch(void* const* d_in, const int* in_sizes, int n_in,
                              void* d_out, int out_size)
{
    const float* x    = (const float*)d_in[0];
    const float* Wqkv = (const float*)d_in[2];
    const float* Wout = (const float*)d_in[3];
    float* out = (float*)d_out;

    cudaFuncSetAttribute(mm_kernel<0>, cudaFuncAttributeMaxDynamicSharedMemorySize, MM_SMEM);
    cudaFuncSetAttribute(mm_kernel<1>, cudaFuncAttributeMaxDynamicSharedMemorySize, MM_SMEM);
    cudaFuncSetAttribute(flash_tc_kernel, cudaFuncAttributeMaxDynamicSharedMemorySize, FTC_SMEM);

    __nv_bfloat16 *pAhi, *pAlo, *pAOhi, *pAOlo, *pBqhi, *pBqlo, *pBohi, *pBolo;
    cudaGetSymbolAddress((void**)&pAhi,  gA_hi);
    cudaGetSymbolAddress((void**)&pAlo,  gA_lo);
    cudaGetSymbolAddress((void**)&pAOhi, gAO_hi);
    cudaGetSymbolAddress((void**)&pAOlo, gAO_lo);
    cudaGetSymbolAddress((void**)&pBqhi, gBq_hi);
    cudaGetSymbolAddress((void**)&pBqlo, gBq_lo);
    cudaGetSymbolAddress((void**)&pBohi, gBo_hi);
    cudaGetSymbolAddress((void**)&pBolo, gBo_lo);
    float *pQ, *pK, *pV, *pAO;
    cudaGetSymbolAddress((void**)&pQ,  g_Q);
    cudaGetSymbolAddress((void**)&pK,  g_K);
    cudaGetSymbolAddress((void**)&pV,  g_V);
    cudaGetSymbolAddress((void**)&pAO, g_AO);
    __half *hQh, *hQl, *hKh, *hKl, *hVh, *hVl;
    cudaGetSymbolAddress((void**)&hQh, gQh);
    cudaGetSymbolAddress((void**)&hQl, gQl);
    cudaGetSymbolAddress((void**)&hKh, gKh);
    cudaGetSymbolAddress((void**)&hKl, gKl);
    cudaGetSymbolAddress((void**)&hVh, gVh);
    cudaGetSymbolAddress((void**)&hVl, gVl);

    // 1) convert projection operands (bf16 hi/lo)
    convA_kernel<<<4096, 256>>>(x, pAhi, pAlo);
    convB_kernel<<<dim3(NQKV / 256, KDIM / 8), 256>>>(Wqkv, NQKV, pBqhi, pBqlo);
    convB_kernel<<<dim3(CC / 256, KDIM / 8), 256>>>(Wout, CC, pBohi, pBolo);

    // 2) QKV projection -> g_Q/g_K/g_V fp32 [B,H,T,D]
    mm_kernel<0><<<dim3(NQKV / TN, BT / TM), 128, MM_SMEM>>>(pAhi, pAlo, pBqhi, pBqlo, nullptr);

    // 3) convert attention tiles to fp16 hi/lo (Q pre-scaled by 1/sqrt(d))
    convQK_kernel<<<4096, 256>>>(pQ, hQh, hQl, 0.08838834764831845f);
    convQK_kernel<<<4096, 256>>>(pK, hKh, hKl, 1.0f);
    convVT_kernel<<<4096, 256>>>(pV, hVh, hVl);

    // 4) causal flash attention on tensor cores
    flash_tc_kernel<<<dim3(16, BB * NH), 128, FTC_SMEM>>>(hQh, hQl, hKh, hKl, hVh, hVl);

    // 5) output projection
    convA_kernel<<<4096, 256>>>(pAO, pAOhi, pAOlo);
    mm_kernel<1><<<dim3(CC / TN, BT / TM), 128, MM_SMEM>>>(pAOhi, pAOlo, pBohi, pBolo, out);
}

// round 6
// speedup vs baseline: 9.7761x; 1.4270x over previous
#include <cuda_runtime.h>
#include <cuda_bf16.h>
#include <cuda_fp16.h>
#include <cstdint>

// Problem constants
#define BB 2
#define TT 2048
#define CC 2048
#define NH 16
#define DH 128
#define BT (BB * TT)        // 4096
#define NQKV (3 * CC)       // 6144
#define KDIM 2048
#define TM 128
#define TN 256

// KC=32 blocking (SW64) for the projection GEMMs
#define KC2 32
#define NKC2 (KDIM / KC2)   // 64
#define ABLK 8192           // 128*32*2 bytes
#define BBLK 16384          // 256*32*2 bytes
#define STG (2 * ABLK + 2 * BBLK)   // 49152
#define NSTAGE 4

#if defined(__CUDA_ARCH_FEAT_SM103_ALL) || defined(__CUDA_ARCH_FEAT_SM100_ALL) || defined(__CUDA_ARCH_FEAT_SM101_ALL)
#define USE_TCGEN05 1
#else
#define USE_TCGEN05 0
#endif

// ---------------------------------------------------------------------------
// Scratch (device globals; allocation is forbidden)
// ---------------------------------------------------------------------------
// SW64 KC=32-blocked bf16 hi/lo operands for projections
__device__ __align__(128) __nv_bfloat16 gA_hi[BT * KDIM];
__device__ __align__(128) __nv_bfloat16 gA_lo[BT * KDIM];
__device__ __align__(128) __nv_bfloat16 gAO_hi[BT * KDIM];
__device__ __align__(128) __nv_bfloat16 gAO_lo[BT * KDIM];
__device__ __align__(128) __nv_bfloat16 gBq_hi[KDIM * NQKV];
__device__ __align__(128) __nv_bfloat16 gBq_lo[KDIM * NQKV];
__device__ __align__(128) __nv_bfloat16 gBo_hi[KDIM * CC];
__device__ __align__(128) __nv_bfloat16 gBo_lo[KDIM * CC];

// SW128 128x128 fp16 hi/lo attention tiles (32KB each tile)
__device__ __align__(128) __half gQh[BB * NH * TT * DH];
__device__ __align__(128) __half gQl[BB * NH * TT * DH];
__device__ __align__(128) __half gKh[BB * NH * TT * DH];
__device__ __align__(128) __half gKl[BB * NH * TT * DH];
__device__ __align__(128) __half gVh[BB * NH * TT * DH];   // V^T tiles
__device__ __align__(128) __half gVl[BB * NH * TT * DH];

// ---------------------------------------------------------------------------
// Helpers
// ---------------------------------------------------------------------------
#define SWZ128(o) ((o) ^ (((o) >> 3) & 0x70))
#define SWZ64(o)  ((o) ^ (((o) >> 3) & 0x30))

__device__ __forceinline__ uint32_t smem_u32(const void* p) {
    uint32_t a;
    asm("{ .reg .u64 t; cvta.to.shared.u64 t, %1; cvt.u32.u64 %0, t; }" : "=r"(a) : "l"(p));
    return a;
}

#if USE_TCGEN05
static constexpr uint64_t DESCB_SW128 =
    (uint64_t(2) << 61) | (uint64_t(1) << 46) | (uint64_t(64) << 32) | (uint64_t(1) << 16);
static constexpr uint64_t DESCB_SW64 =
    (uint64_t(4) << 61) | (uint64_t(1) << 46) | (uint64_t(32) << 32) | (uint64_t(1) << 16);
#define MAKE_DESC128(a) (DESCB_SW128 | ((uint64_t)((a) >> 4) & 0x3FFF))
#define MAKE_DESC64(a)  (DESCB_SW64  | ((uint64_t)((a) >> 4) & 0x3FFF))

__device__ __forceinline__ uint32_t elect1() {
    uint32_t p;
    asm volatile("{\n\t.reg .pred p;\n\telect.sync _|p, 0xFFFFFFFF;\n\tselp.b32 %0, 1, 0, p;\n\t}" : "=r"(p));
    return p;
}
__device__ __forceinline__ void mbar_init(uint32_t a, uint32_t c) {
    asm volatile("mbarrier.init.shared.b64 [%0], %1;" :: "r"(a), "r"(c) : "memory");
}
__device__ __forceinline__ void mbar_expect(uint32_t a, uint32_t tx) {
    asm volatile("mbarrier.arrive.expect_tx.shared.b64 _, [%0], %1;" :: "r"(a), "r"(tx) : "memory");
}
__device__ __forceinline__ void mbar_arrive(uint32_t a) {
    asm volatile("mbarrier.arrive.release.cta.shared.b64 _, [%0];" :: "r"(a) : "memory");
}
__device__ __forceinline__ void mbar_wait_acq(uint32_t a, uint32_t ph) {
    asm volatile(
        "{\n\t.reg .pred P;\n"
        "WL_%=:\n\t"
        "mbarrier.try_wait.parity.acquire.cta.shared::cta.b64 P, [%0], %1, 0x989680;\n\t"
        "@P bra WD_%=;\n\t"
        "bra WL_%=;\n"
        "WD_%=:\n\t}"
        :: "r"(a), "r"(ph) : "memory");
}
__device__ __forceinline__ void mbar_wait_rlx(uint32_t a, uint32_t ph) {
    asm volatile(
        "{\n\t.reg .pred P;\n"
        "WL_%=:\n\t"
        "mbarrier.try_wait.parity.relaxed.cta.shared::cta.b64 P, [%0], %1, 0x989680;\n\t"
        "@P bra WD_%=;\n\t"
        "bra WL_%=;\n"
        "WD_%=:\n\t}"
        :: "r"(a), "r"(ph) : "memory");
}
__device__ __forceinline__ void bulk_g2s(uint32_t dst, const void* src, uint32_t n, uint32_t mbar) {
    asm volatile(
        "cp.async.bulk.shared::cta.global.mbarrier::complete_tx::bytes [%0], [%1], %2, [%3];"
        :: "r"(dst), "l"(src), "r"(n), "r"(mbar) : "memory");
}
__device__ __forceinline__ void tc_alloc(uint32_t smem_res, uint32_t ncols) {
    asm volatile("tcgen05.alloc.cta_group::1.sync.aligned.shared::cta.b32 [%0], %1;"
                 :: "r"(smem_res), "r"(ncols) : "memory");
}
__device__ __forceinline__ void tc_dealloc(uint32_t tmem, uint32_t ncols) {
    asm volatile("tcgen05.dealloc.cta_group::1.sync.aligned.b32 %0, %1;" :: "r"(tmem), "r"(ncols));
}
__device__ __forceinline__ void tc_commit(uint32_t mbar) {
    asm volatile("tcgen05.commit.cta_group::1.mbarrier::arrive::one.shared::cluster.b64 [%0];"
                 :: "r"(mbar) : "memory");
}
__device__ __forceinline__ void tc_fence_before() {
    asm volatile("tcgen05.fence::before_thread_sync;" ::: "memory");
}
__device__ __forceinline__ void tc_fence_after() {
    asm volatile("tcgen05.fence::after_thread_sync;" ::: "memory");
}
__device__ __forceinline__ void tc_wait_ld() {
    asm volatile("tcgen05.wait::ld.sync.aligned;" ::: "memory");
}
__device__ __forceinline__ void tc_wait_st() {
    asm volatile("tcgen05.wait::st.sync.aligned;" ::: "memory");
}
__device__ __forceinline__ void mma_f16_ss(uint32_t d, uint64_t a, uint64_t b, uint32_t idesc, uint32_t en) {
    asm volatile(
        "{\n\t.reg .pred p;\n\t"
        "setp.ne.u32 p, %5, 0;\n\t"
        "tcgen05.mma.cta_group::1.kind::f16 [%0], %1, %2, %3, {%4, %4, %4, %4}, p;\n\t}"
        :: "r"(d), "l"(a), "l"(b), "r"(idesc), "r"(0u), "r"(en) : "memory");
}
__device__ __forceinline__ void mma_f16_ts(uint32_t d, uint32_t a, uint64_t b, uint32_t idesc, uint32_t en) {
    asm volatile(
        "{\n\t.reg .pred p;\n\t"
        "setp.ne.u32 p, %5, 0;\n\t"
        "tcgen05.mma.cta_group::1.kind::f16 [%0], [%1], %2, %3, {%4, %4, %4, %4}, p;\n\t}"
        :: "r"(d), "r"(a), "l"(b), "r"(idesc), "r"(0u), "r"(en) : "memory");
}
#define TC_LD_32X32B_X32(r, tmem_addr) \
    asm volatile( \
        "tcgen05.ld.sync.aligned.32x32b.x32.b32 " \
        "{%0, %1, %2, %3, %4, %5, %6, %7, " \
        " %8, %9, %10, %11, %12, %13, %14, %15, " \
        " %16, %17, %18, %19, %20, %21, %22, %23, " \
        " %24, %25, %26, %27, %28, %29, %30, %31}, [%32];" \
        : "=r"((r)[0]),  "=r"((r)[1]),  "=r"((r)[2]),  "=r"((r)[3]), \
          "=r"((r)[4]),  "=r"((r)[5]),  "=r"((r)[6]),  "=r"((r)[7]), \
          "=r"((r)[8]),  "=r"((r)[9]),  "=r"((r)[10]), "=r"((r)[11]), \
          "=r"((r)[12]), "=r"((r)[13]), "=r"((r)[14]), "=r"((r)[15]), \
          "=r"((r)[16]), "=r"((r)[17]), "=r"((r)[18]), "=r"((r)[19]), \
          "=r"((r)[20]), "=r"((r)[21]), "=r"((r)[22]), "=r"((r)[23]), \
          "=r"((r)[24]), "=r"((r)[25]), "=r"((r)[26]), "=r"((r)[27]), \
          "=r"((r)[28]), "=r"((r)[29]), "=r"((r)[30]), "=r"((r)[31]) \
        : "r"(tmem_addr))
#define TC_ST_32X32B_X32(tmem_addr, r) \
    asm volatile( \
        "tcgen05.st.sync.aligned.32x32b.x32.b32 [%0], " \
        "{%1, %2, %3, %4, %5, %6, %7, %8, " \
        " %9, %10, %11, %12, %13, %14, %15, %16, " \
        " %17, %18, %19, %20, %21, %22, %23, %24, " \
        " %25, %26, %27, %28, %29, %30, %31, %32};" \
        :: "r"(tmem_addr), \
           "r"((r)[0]),  "r"((r)[1]),  "r"((r)[2]),  "r"((r)[3]), \
           "r"((r)[4]),  "r"((r)[5]),  "r"((r)[6]),  "r"((r)[7]), \
           "r"((r)[8]),  "r"((r)[9]),  "r"((r)[10]), "r"((r)[11]), \
           "r"((r)[12]), "r"((r)[13]), "r"((r)[14]), "r"((r)[15]), \
           "r"((r)[16]), "r"((r)[17]), "r"((r)[18]), "r"((r)[19]), \
           "r"((r)[20]), "r"((r)[21]), "r"((r)[22]), "r"((r)[23]), \
           "r"((r)[24]), "r"((r)[25]), "r"((r)[26]), "r"((r)[27]), \
           "r"((r)[28]), "r"((r)[29]), "r"((r)[30]), "r"((r)[31]) \
        : "memory")

// bf16 GEMM idesc: dtype F32, atype/btype BF16, N=256, M=128
#define MM_IDESC ((1u<<4) | (1u<<7) | (1u<<10) | (32u<<17) | (8u<<24))
// fp16 attention idesc: dtype F32, atype/btype F16(0), N=128, M=128
#define FA_IDESC ((1u<<4) | (16u<<17) | (8u<<24))
#endif // USE_TCGEN05

// ---------------------------------------------------------------------------
// Conversion kernels: fp32 -> SW64 KC=32-blocked bf16 hi/lo.
// ---------------------------------------------------------------------------
__global__ __launch_bounds__(256) void convA_kernel(
    const float* __restrict__ src, __nv_bfloat16* __restrict__ hi, __nv_bfloat16* __restrict__ lo)
{
    int e = blockIdx.x * 256 + threadIdx.x;
    int m = e >> 8;
    int k = (e & 255) << 3;
    float v[8];
    *(float4*)&v[0] = *(const float4*)&src[(size_t)m * KDIM + k];
    *(float4*)&v[4] = *(const float4*)&src[(size_t)m * KDIM + k + 4];
    __nv_bfloat16 hb[8], lb[8];
#pragma unroll
    for (int i = 0; i < 8; i++) {
        hb[i] = __float2bfloat16(v[i]);
        lb[i] = __float2bfloat16(v[i] - __bfloat162float(hb[i]));
    }
    int mt = m >> 7, r = m & 127, kc = k >> 5, kcol = k & 31;
    size_t blk = (size_t)(mt * NKC2 + kc) * ABLK;         // bytes
    uint32_t off = SWZ64((uint32_t)(r * 64 + kcol * 2));
    *(uint4*)((char*)hi + blk + off) = *(uint4*)hb;
    *(uint4*)((char*)lo + blk + off) = *(uint4*)lb;
}

__global__ __launch_bounds__(256) void convB_kernel(
    const float* __restrict__ W, int N,
    __nv_bfloat16* __restrict__ hi, __nv_bfloat16* __restrict__ lo)
{
    int n = blockIdx.x * 256 + threadIdx.x;
    int k = blockIdx.y * 8;
    float v[8];
#pragma unroll
    for (int i = 0; i < 8; i++) v[i] = W[(size_t)(k + i) * N + n];
    __nv_bfloat16 hb[8], lb[8];
#pragma unroll
    for (int i = 0; i < 8; i++) {
        hb[i] = __float2bfloat16(v[i]);
        lb[i] = __float2bfloat16(v[i] - __bfloat162float(hb[i]));
    }
    int nt = n >> 8, nr = n & 255, kc = k >> 5, kcol = k & 31;
    size_t blk = (size_t)(nt * NKC2 + kc) * BBLK;
    uint32_t off = SWZ64((uint32_t)(nr * 64 + kcol * 2));
    *(uint4*)((char*)hi + blk + off) = *(uint4*)hb;
    *(uint4*)((char*)lo + blk + off) = *(uint4*)lb;
}

// ---------------------------------------------------------------------------
// tcgen05 GEMM: 128x256 tile/CTA, KC=32 SW64, 4-stage pipeline.
// MODE 0: QKV — epilogue writes fp16 hi/lo SW128 attention tiles (Q scaled, V^T).
// MODE 1: out projection — row-major fp32.
// ---------------------------------------------------------------------------
#define MM_SMEM (1024 + NSTAGE * STG)

template <int MODE>
__global__ __launch_bounds__(128) void mm_kernel(
    const __nv_bfloat16* __restrict__ Ahi, const __nv_bfloat16* __restrict__ Alo,
    const __nv_bfloat16* __restrict__ Bhi, const __nv_bfloat16* __restrict__ Blo,
    float* __restrict__ Cout)
{
    extern __shared__ char smem[];
    const int tid = threadIdx.x;
    const int nt = blockIdx.x, mt = blockIdx.y;

#if USE_TCGEN05
    __shared__ __align__(8) uint64_t s_ctrl[16];  // [0]=tmem, [1..4]=ful, [5..8]=don, [9]=FIN
    const uint32_t TMP = smem_u32(&s_ctrl[0]);
    uint32_t ful[NSTAGE], don[NSTAGE];
#pragma unroll
    for (int s = 0; s < NSTAGE; s++) {
        ful[s] = smem_u32(&s_ctrl[1 + s]);
        don[s] = smem_u32(&s_ctrl[5 + s]);
    }
    const uint32_t FIN = smem_u32(&s_ctrl[9]);

    const uint32_t sb = smem_u32(smem);
    const uint32_t ab = (sb + 1023u) & ~1023u;
    char* smA = smem + (ab - sb);
    const int wid = tid >> 5, lane = tid & 31;

    if (wid == 0) tc_alloc(TMP, 256);
    if (tid == 0) {
#pragma unroll
        for (int s = 0; s < NSTAGE; s++) { mbar_init(ful[s], 1); mbar_init(don[s], 1); }
        mbar_init(FIN, 1);
    }
    __syncthreads();
    uint32_t tmem;
    asm volatile("ld.shared.b32 %0, [%1];" : "=r"(tmem) : "r"(TMP));

    const char* aB = (const char*)Ahi + (size_t)mt * NKC2 * ABLK;
    const char* aL = (const char*)Alo + (size_t)mt * NKC2 * ABLK;
    const char* bB = (const char*)Bhi + (size_t)nt * NKC2 * BBLK;
    const char* bL = (const char*)Blo + (size_t)nt * NKC2 * BBLK;

    if (wid == 0) {
        const uint32_t ep = elect1();
        int fph[NSTAGE] = {0, 0, 0, 0}, dph[NSTAGE] = {0, 0, 0, 0};

        if (ep) {
#pragma unroll
            for (int s = 0; s < NSTAGE; s++) {
                uint32_t st = ab + s * STG;
                mbar_expect(ful[s], STG);
                bulk_g2s(st,             aB + (size_t)s * ABLK, ABLK, ful[s]);
                bulk_g2s(st + ABLK,      aL + (size_t)s * ABLK, ABLK, ful[s]);
                bulk_g2s(st + 2 * ABLK,  bB + (size_t)s * BBLK, BBLK, ful[s]);
                bulk_g2s(st + 2 * ABLK + BBLK, bL + (size_t)s * BBLK, BBLK, ful[s]);
            }
        }
        for (int kc = 0; kc < NKC2; kc++) {
            int st = kc & (NSTAGE - 1);
            uint32_t sbase = ab + st * STG;
            mbar_wait_rlx(ful[st], fph[st]); fph[st] ^= 1;
            if (ep) {
                uint64_t ah = MAKE_DESC64(sbase);
                uint64_t al = MAKE_DESC64(sbase + ABLK);
                uint64_t bh = MAKE_DESC64(sbase + 2 * ABLK);
                uint64_t bl = MAKE_DESC64(sbase + 2 * ABLK + BBLK);
#pragma unroll
                for (int ks = 0; ks < 2; ks++) {
                    uint64_t o = (uint64_t)(ks * 2);
                    uint32_t first = (kc == 0 && ks == 0) ? 0u : 1u;
                    mma_f16_ss(tmem, ah + o, bh + o, MM_IDESC, first);
                    mma_f16_ss(tmem, ah + o, bl + o, MM_IDESC, 1u);
                    mma_f16_ss(tmem, al + o, bh + o, MM_IDESC, 1u);
                }
                tc_commit(don[st]);
            }
            int pv = kc - 1;
            if (pv >= 0 && pv + NSTAGE < NKC2) {
                int ps = pv & (NSTAGE - 1);
                mbar_wait_rlx(don[ps], dph[ps]); dph[ps] ^= 1;
                if (ep) {
                    size_t nk = (size_t)(pv + NSTAGE);
                    uint32_t pb = ab + ps * STG;
                    mbar_expect(ful[ps], STG);
                    bulk_g2s(pb,             aB + nk * ABLK, ABLK, ful[ps]);
                    bulk_g2s(pb + ABLK,      aL + nk * ABLK, ABLK, ful[ps]);
                    bulk_g2s(pb + 2 * ABLK,  bB + nk * BBLK, BBLK, ful[ps]);
                    bulk_g2s(pb + 2 * ABLK + BBLK, bL + nk * BBLK, BBLK, ful[ps]);
                }
            }
        }
#pragma unroll
        for (int s = 0; s < NSTAGE; s++) { mbar_wait_rlx(don[s], dph[s]); }
        if (ep) mbar_arrive(FIN);
    }

    mbar_wait_acq(FIN, 0);
    tc_fence_after();

    // -------------------- epilogue --------------------
    const int mBase = mt * TM + wid * 32;       // warp's 32 rows
    const int nBase = nt * TN;
    float* sbuf = (float*)smA + wid * (32 * 33);

    if (MODE == 0) {
        const int b = mBase >> 11;
        const int tile = (mBase & 2047) >> 7;   // 128-row tile within T
        const int r0 = mBase & 127;             // = wid*32
        const int which = nBase >> 11;          // 0=q,1=k,2=v
        const int h0 = (nBase & 2047) >> 7;
        const float qscale = 0.08838834764831845f;

#pragma unroll 1
        for (int ch = 0; ch < 8; ch++) {
            uint32_t rg[32];
            TC_LD_32X32B_X32(rg, tmem + ch * 32);
            tc_wait_ld();
            const int h = h0 + (ch >> 2);
            const int d0 = (ch & 3) * 32;
            const size_t tbase = ((size_t)(b * NH + h) * 16 + tile) * 32768;

            if (which != 2) {
                // Q/K: thread = m-row, 32 contiguous d values.
                const float sc = (which == 0) ? qscale : 1.0f;
                __half hb[32], lb[32];
#pragma unroll
                for (int c = 0; c < 32; c++) {
                    float f = __uint_as_float(rg[c]) * sc;
                    __half hh = __float2half_rn(f);
                    hb[c] = hh;
                    lb[c] = __float2half_rn(f - __half2float(hh));
                }
                const int r = r0 + lane;
                const int atom = (r >> 3) + (d0 >> 6) * 16;
                const uint32_t base = (uint32_t)(atom * 1024 + (r & 7) * 128 + (d0 & 63) * 2);
                char* dh = (char*)((which == 0) ? gQh : gKh) + tbase;
                char* dl = (char*)((which == 0) ? gQl : gKl) + tbase;
#pragma unroll
                for (int q = 0; q < 4; q++) {
                    uint32_t o = SWZ128(base + q * 16);
                    *(uint4*)(dh + o) = ((uint4*)hb)[q];
                    *(uint4*)(dl + o) = ((uint4*)lb)[q];
                }
            } else {
                // V: transpose via smem; thread owns d-row = d0+lane over warp's 32 keys.
#pragma unroll
                for (int c = 0; c < 32; c++) sbuf[lane * 33 + c] = __uint_as_float(rg[c]);
                __syncwarp();
                const int d = d0 + lane;
                const int ac2 = wid >> 1;            // (wid*32)>>6
                const int ic2 = (wid & 1) * 32;
                const int atom2 = (d >> 3) + ac2 * 16;
                const uint32_t base2 = (uint32_t)(atom2 * 1024 + (d & 7) * 128 + ic2 * 2);
                __half hv[32], lv[32];
#pragma unroll
                for (int rr = 0; rr < 32; rr++) {
                    float f = sbuf[rr * 33 + lane];
                    __half hh = __float2half_rn(f);
                    hv[rr] = hh;
                    lv[rr] = __float2half_rn(f - __half2float(hh));
                }
#pragma unroll
                for (int q = 0; q < 4; q++) {
                    uint32_t o = SWZ128(base2 + q * 16);
                    *(uint4*)((char*)gVh + tbase + o) = ((uint4*)hv)[q];
                    *(uint4*)((char*)gVl + tbase + o) = ((uint4*)lv)[q];
                }
                __syncwarp();
            }
        }
    } else {
        // MODE 1: row-major fp32 out via smem transpose (coalesced stores)
#pragma unroll 1
        for (int ch = 0; ch < 8; ch++) {
            uint32_t rg[32];
            TC_LD_32X32B_X32(rg, tmem + ch * 32);
            tc_wait_ld();
#pragma unroll
            for (int c = 0; c < 32; c++) sbuf[lane * 33 + c] = __uint_as_float(rg[c]);
            __syncwarp();
            int ncol0 = nBase + ch * 32;
#pragma unroll 4
            for (int rr = 0; rr < 32; rr++) {
                int m = mBase + rr;
                Cout[(size_t)m * CC + ncol0 + lane] = sbuf[rr * 33 + lane];
            }
            __syncwarp();
        }
    }
    __syncthreads();
    if (wid == 0) tc_dealloc(tmem, 256);
#endif
}

// ---------------------------------------------------------------------------
// tcgen05 flash attention (causal). 128 threads; q-tile 128; key tile 128.
// TMEM: S[0..127] fp32, O[128..255] fp32, P[256..319] fp16x2.
// Epilogue writes SW64 KC=32-blocked bf16 hi/lo AO for the out projection.
// ---------------------------------------------------------------------------
#define FTC_SMEM (1024 + 6 * 32768)

__global__ __launch_bounds__(128, 1) void flash_tc_kernel(
    const __half* __restrict__ pQh, const __half* __restrict__ pQl,
    const __half* __restrict__ pKh, const __half* __restrict__ pKl,
    const __half* __restrict__ pVh, const __half* __restrict__ pVl)
{
#if USE_TCGEN05
    extern __shared__ char smem[];
    __shared__ __align__(8) uint64_t ctrl[8];
    const uint32_t TMP = smem_u32(&ctrl[0]);
    const uint32_t QF  = smem_u32(&ctrl[1]);
    const uint32_t KVF = smem_u32(&ctrl[2]);
    const uint32_t SD  = smem_u32(&ctrl[3]);
    const uint32_t PD  = smem_u32(&ctrl[4]);

    const int tid = threadIdx.x, wid = tid >> 5, lane = tid & 31;
    const int bh = blockIdx.y;
    const int qt = (int)gridDim.x - 1 - (int)blockIdx.x;   // long CTAs first

    const uint32_t sb = smem_u32(smem);
    const uint32_t ab = (sb + 1023u) & ~1023u;
    const uint32_t sQh = ab, sQl = ab + 32768, sKh = ab + 65536,
                   sKl = ab + 98304, sVh = ab + 131072, sVl = ab + 163840;

    if (wid == 0) tc_alloc(TMP, 512);
    if (tid == 0) { mbar_init(QF, 1); mbar_init(KVF, 1); mbar_init(SD, 1); mbar_init(PD, 1); }
    __syncthreads();
    uint32_t tmem;
    asm volatile("ld.shared.b32 %0, [%1];" : "=r"(tmem) : "r"(TMP));
    const uint32_t tS = tmem, tO = tmem + 128, tP = tmem + 256;
    const uint32_t woff = (uint32_t)wid << 21;

    const size_t headBase = (size_t)bh * 16 * 16384;       // elements; 16 tiles/head
    const size_t qOff = headBase + (size_t)qt * 16384;

    if (wid == 0 && elect1()) {
        mbar_expect(QF, 65536);
        bulk_g2s(sQh, pQh + qOff, 32768, QF);
        bulk_g2s(sQl, pQl + qOff, 32768, QF);
        mbar_expect(KVF, 131072);
        bulk_g2s(sKh, pKh + headBase, 32768, KVF);
        bulk_g2s(sKl, pKl + headBase, 32768, KVF);
        bulk_g2s(sVh, pVh + headBase, 32768, KVF);
        bulk_g2s(sVl, pVl + headBase, 32768, KVF);
    }

    const float NEG_INF = __int_as_float(0xff800000);
    float m = NEG_INF, l = 0.f;

    for (int j = 0; j <= qt; j++) {
        const int ph = j & 1;
        if (wid == 0) {
            if (j == 0) mbar_wait_rlx(QF, 0);
            mbar_wait_rlx(KVF, ph);
            if (elect1()) {
                uint64_t dQh = MAKE_DESC128(sQh), dQl = MAKE_DESC128(sQl);
                uint64_t dKh = MAKE_DESC128(sKh), dKl = MAKE_DESC128(sKl);
#pragma unroll
                for (int ks = 0; ks < 8; ks++) {
                    uint64_t o = (uint64_t)((ks & 3) * 2 + (ks >> 2) * 1024);
                    mma_f16_ss(tS, dQh + o, dKh + o, FA_IDESC, ks == 0 ? 0u : 1u);
                    mma_f16_ss(tS, dQh + o, dKl + o, FA_IDESC, 1u);
                    mma_f16_ss(tS, dQl + o, dKh + o, FA_IDESC, 1u);
                }
                tc_commit(SD);
            }
        }
        mbar_wait_acq(SD, ph);
        tc_fence_after();

        float s[128];
#pragma unroll
        for (int c4 = 0; c4 < 4; c4++)
            TC_LD_32X32B_X32(((uint32_t*)s) + c4 * 32, tS + woff + c4 * 32);
        tc_wait_ld();

        if (j == qt) {
            int qrow = wid * 32 + lane;
#pragma unroll
            for (int c = 0; c < 128; c++)
                if (c > qrow) s[c] = NEG_INF;
        }
        float mx = m;
#pragma unroll
        for (int c = 0; c < 128; c++) mx = fmaxf(mx, s[c]);
        float alpha = __expf(m - mx);
        m = mx;
        float ls = 0.f;
#pragma unroll
        for (int c = 0; c < 128; c++) {
            float p = __expf(s[c] - mx);
            s[c] = p;
            ls += p;
        }
        l = l * alpha + ls;

        {
            uint32_t pk[32];
#pragma unroll
            for (int c = 0; c < 32; c++) {
                __half2 h2 = __floats2half2_rn(s[2 * c], s[2 * c + 1]);
                pk[c] = *reinterpret_cast<uint32_t*>(&h2);
            }
            TC_ST_32X32B_X32(tP + woff, pk);
#pragma unroll
            for (int c = 0; c < 32; c++) {
                __half2 h2 = __floats2half2_rn(s[64 + 2 * c], s[64 + 2 * c + 1]);
                pk[c] = *reinterpret_cast<uint32_t*>(&h2);
            }
            TC_ST_32X32B_X32(tP + woff + 32, pk);
            tc_wait_st();
        }

        if (j > 0 && !__all_sync(0xffffffffu, alpha == 1.0f)) {
#pragma unroll 1
            for (int c4 = 0; c4 < 4; c4++) {
                uint32_t o[32];
                TC_LD_32X32B_X32(o, tO + woff + c4 * 32);
                tc_wait_ld();
#pragma unroll
                for (int c = 0; c < 32; c++)
                    o[c] = __float_as_uint(__uint_as_float(o[c]) * alpha);
                TC_ST_32X32B_X32(tO + woff + c4 * 32, o);
            }
            tc_wait_st();
        }
        tc_fence_before();
        __syncthreads();

        if (wid == 0 && elect1()) {
            tc_fence_after();
            uint64_t dVh = MAKE_DESC128(sVh), dVl = MAKE_DESC128(sVl);
#pragma unroll
            for (int ks = 0; ks < 8; ks++) {
                uint64_t o = (uint64_t)((ks & 3) * 2 + (ks >> 2) * 1024);
                mma_f16_ts(tO, tP + ks * 8, dVh + o, FA_IDESC, (j == 0 && ks == 0) ? 0u : 1u);
            }
#pragma unroll
            for (int ks = 0; ks < 8; ks++) {
                uint64_t o = (uint64_t)((ks & 3) * 2 + (ks >> 2) * 1024);
                mma_f16_ts(tO, tP + ks * 8, dVl + o, FA_IDESC, 1u);
            }
            tc_commit(PD);
        }
        mbar_wait_acq(PD, ph);
        tc_fence_after();

        if (j < qt && wid == 0 && elect1()) {
            size_t kOff = headBase + (size_t)(j + 1) * 16384;
            mbar_expect(KVF, 131072);
            bulk_g2s(sKh, pKh + kOff, 32768, KVF);
            bulk_g2s(sKl, pKl + kOff, 32768, KVF);
            bulk_g2s(sVh, pVh + kOff, 32768, KVF);
            bulk_g2s(sVl, pVl + kOff, 32768, KVF);
        }
    }

    // epilogue: O/l -> SW64 KC=32-blocked bf16 hi/lo AO (direct, no transpose)
    const float invl = 1.0f / l;
    const int b = bh >> 4, h = bh & 15;
    const int r = wid * 32 + lane;                 // local q-row
    const int mt2 = b * 16 + qt;                   // 128-row block index
#pragma unroll 1
    for (int ch = 0; ch < 4; ch++) {
        uint32_t o[32];
        TC_LD_32X32B_X32(o, tO + woff + ch * 32);
        tc_wait_ld();
        __nv_bfloat16 hb[32], lb[32];
#pragma unroll
        for (int c = 0; c < 32; c++) {
            float f = __uint_as_float(o[c]) * invl;
            __nv_bfloat16 hh = __float2bfloat16(f);
            hb[c] = hh;
            lb[c] = __float2bfloat16(f - __bfloat162float(hh));
        }
        const int kc = h * 4 + ch;
        const size_t blk = (size_t)(mt2 * NKC2 + kc) * ABLK;
        const uint32_t base = (uint32_t)(r * 64);
#pragma unroll
        for (int q = 0; q < 4; q++) {
            uint32_t off = SWZ64(base + q * 16);
            *(uint4*)((char*)gAO_hi + blk + off) = ((uint4*)hb)[q];
            *(uint4*)((char*)gAO_lo + blk + off) = ((uint4*)lb)[q];
        }
    }
    __syncthreads();
    if (wid == 0) tc_dealloc(tmem, 512);
#endif
}

// ---------------------------------------------------------------------------
extern "C" void kernel_launch(void* const* d_in, const int* in_sizes, int n_in,
                              void* d_out, int out_size)
{
    const float* x    = (const float*)d_in[0];
    const float* Wqkv = (const float*)d_in[2];
    const float* Wout = (const float*)d_in[3];
    float* out = (float*)d_out;

    cudaFuncSetAttribute(mm_kernel<0>, cudaFuncAttributeMaxDynamicSharedMemorySize, MM_SMEM);
    cudaFuncSetAttribute(mm_kernel<1>, cudaFuncAttributeMaxDynamicSharedMemorySize, MM_SMEM);
    cudaFuncSetAttribute(flash_tc_kernel, cudaFuncAttributeMaxDynamicSharedMemorySize, FTC_SMEM);

    __nv_bfloat16 *pAhi, *pAlo, *pAOhi, *pAOlo, *pBqhi, *pBqlo, *pBohi, *pBolo;
    cudaGetSymbolAddress((void**)&pAhi,  gA_hi);
    cudaGetSymbolAddress((void**)&pAlo,  gA_lo);
    cudaGetSymbolAddress((void**)&pAOhi, gAO_hi);
    cudaGetSymbolAddress((void**)&pAOlo, gAO_lo);
    cudaGetSymbolAddress((void**)&pBqhi, gBq_hi);
    cudaGetSymbolAddress((void**)&pBqlo, gBq_lo);
    cudaGetSymbolAddress((void**)&pBohi, gBo_hi);
    cudaGetSymbolAddress((void**)&pBolo, gBo_lo);
    __half *hQh, *hQl, *hKh, *hKl, *hVh, *hVl;
    cudaGetSymbolAddress((void**)&hQh, gQh);
    cudaGetSymbolAddress((void**)&hQl, gQl);
    cudaGetSymbolAddress((void**)&hKh, gKh);
    cudaGetSymbolAddress((void**)&hKl, gKl);
    cudaGetSymbolAddress((void**)&hVh, gVh);
    cudaGetSymbolAddress((void**)&hVl, gVl);

    // 1) convert inputs (SW64 KC=32 blocked bf16 hi/lo)
    convA_kernel<<<4096, 256>>>(x, pAhi, pAlo);
    convB_kernel<<<dim3(NQKV / 256, KDIM / 8), 256>>>(Wqkv, NQKV, pBqhi, pBqlo);
    convB_kernel<<<dim3(CC / 256, KDIM / 8), 256>>>(Wout, CC, pBohi, pBolo);

    // 2) QKV projection; epilogue emits fp16 hi/lo attention tiles directly
    mm_kernel<0><<<dim3(NQKV / TN, BT / TM), 128, MM_SMEM>>>(pAhi, pAlo, pBqhi, pBqlo, nullptr);

    // 3) causal flash attention; epilogue emits bf16 hi/lo AO blocks directly
    flash_tc_kernel<<<dim3(16, BB * NH), 128, FTC_SMEM>>>(hQh, hQl, hKh, hKl, hVh, hVl);

    // 4) output projection
    mm_kernel<1><<<dim3(CC / TN, BT / TM), 128, MM_SMEM>>>(pAOhi, pAOlo, pBohi, pBolo, out);
}